// round 2
// baseline (speedup 1.0000x reference)
#include <cuda_runtime.h>

#define BB 2
#define TT 1024
#define EE 1024
#define HH 16
#define HD 64
#define NTOK (BB*TT)      // 2048
#define NBH  (BB*HH)      // 32
#define ALPHA 0.25f       // (1/sqrt(HD)) / TEMP = 0.125 * 2

// ---------------- device scratch (no allocation allowed) ----------------
// projections: 0=Q,1=Q2,2=Q3,3=K,4=V   each [NTOK, EE]
__device__ float  g_P[5][(size_t)NTOK * EE];
__device__ float  g_E2[(size_t)NBH * TT * TT];   // exp scores tensor 2
__device__ float  g_E3[(size_t)NBH * TT * TT];   // exp scores tensor 3
__device__ float  g_AO[(size_t)NTOK * EE];       // attention output pre-projection
__device__ double g_sums[3 * NBH];               // global softmax denominators

// ---------------- zero the softmax sums (must run each replay) ----------
__global__ void k_zero_sums() {
    int i = threadIdx.x;
    if (i < 3 * NBH) g_sums[i] = 0.0;
}

// ---------------- generic 128x128x16 NT GEMM + bias ---------------------
// C[M,N] = A[M,K] * W[N,K]^T + bias[N]
// grid: (N/128, M/128), block: 256 threads, 8x8 per thread
__global__ __launch_bounds__(256) void k_gemm_bias(
    const float* __restrict__ A, const float* __restrict__ W,
    const float* __restrict__ bias, float* __restrict__ C,
    int K, int lda, int ldb, int ldc)
{
    __shared__ float As[16][129];
    __shared__ float Bs[16][129];
    const int tid = threadIdx.x;
    const int tx = tid & 15, ty = tid >> 4;
    const int m0 = blockIdx.y * 128, n0 = blockIdx.x * 128;

    float acc[8][8] = {};
    for (int k0 = 0; k0 < K; k0 += 16) {
#pragma unroll
        for (int e = 0; e < 8; e++) {
            int lin = tid + e * 256;          // 0..2047
            int r = lin >> 4, kk = lin & 15;
            As[kk][r] = A[(size_t)(m0 + r) * lda + k0 + kk];
            Bs[kk][r] = W[(size_t)(n0 + r) * ldb + k0 + kk];
        }
        __syncthreads();
#pragma unroll
        for (int kk = 0; kk < 16; kk++) {
            float a[8], b[8];
#pragma unroll
            for (int i = 0; i < 8; i++) a[i] = As[kk][ty + 16 * i];
#pragma unroll
            for (int j = 0; j < 8; j++) b[j] = Bs[kk][tx + 16 * j];
#pragma unroll
            for (int i = 0; i < 8; i++)
#pragma unroll
                for (int j = 0; j < 8; j++)
                    acc[i][j] = fmaf(a[i], b[j], acc[i][j]);
        }
        __syncthreads();
    }
#pragma unroll
    for (int i = 0; i < 8; i++) {
        int row = m0 + ty + 16 * i;
#pragma unroll
        for (int j = 0; j < 8; j++) {
            int col = n0 + tx + 16 * j;
            C[(size_t)row * ldc + col] = acc[i][j] + bias[col];
        }
    }
}

// ---------------- scores: exp((Qh Kh^T) * ALPHA), fused global sum ------
// grid: (8, 8, 96)  z = tensor*32 + bh ; block 256, 8x8/thread, K=64
__global__ __launch_bounds__(256) void k_score(float* __restrict__ E1out)
{
    __shared__ float As[16][129];
    __shared__ float Bs[16][129];
    __shared__ float red[256];

    const int zz = blockIdx.z;
    const int tensor = zz >> 5;          // 0,1,2
    const int bh = zz & 31;
    const int b = bh >> 4, h = bh & 15;

    const float* Aq = g_P[tensor] + (size_t)b * TT * EE + h * HD;
    const float* Bk = g_P[3]      + (size_t)b * TT * EE + h * HD;
    float* Eo = (tensor == 0) ? E1out : (tensor == 1 ? g_E2 : g_E3);
    Eo += (size_t)bh * TT * TT;

    const int tid = threadIdx.x;
    const int tx = tid & 15, ty = tid >> 4;
    const int m0 = blockIdx.y * 128, n0 = blockIdx.x * 128;

    float acc[8][8] = {};
#pragma unroll
    for (int k0 = 0; k0 < 64; k0 += 16) {
#pragma unroll
        for (int e = 0; e < 8; e++) {
            int lin = tid + e * 256;
            int r = lin >> 4, kk = lin & 15;
            As[kk][r] = Aq[(size_t)(m0 + r) * EE + k0 + kk];
            Bs[kk][r] = Bk[(size_t)(n0 + r) * EE + k0 + kk];
        }
        __syncthreads();
#pragma unroll
        for (int kk = 0; kk < 16; kk++) {
            float a[8], bb[8];
#pragma unroll
            for (int i = 0; i < 8; i++) a[i] = As[kk][ty + 16 * i];
#pragma unroll
            for (int j = 0; j < 8; j++) bb[j] = Bs[kk][tx + 16 * j];
#pragma unroll
            for (int i = 0; i < 8; i++)
#pragma unroll
                for (int j = 0; j < 8; j++)
                    acc[i][j] = fmaf(a[i], bb[j], acc[i][j]);
        }
        __syncthreads();
    }

    float lsum = 0.f;
#pragma unroll
    for (int i = 0; i < 8; i++) {
        int row = m0 + ty + 16 * i;
#pragma unroll
        for (int j = 0; j < 8; j++) {
            int col = n0 + tx + 16 * j;
            float v = __expf(acc[i][j] * ALPHA);
            Eo[(size_t)row * TT + col] = v;
            lsum += v;
        }
    }
    // block reduction, one double atomic per block
    red[tid] = lsum;
    __syncthreads();
    for (int s = 128; s > 0; s >>= 1) {
        if (tid < s) red[tid] += red[tid + s];
        __syncthreads();
    }
    if (tid == 0) atomicAdd(&g_sums[zz], (double)red[0]);
}

// ---------------- AV: attn_out = ((a1+a2+a3)/3) @ V, fused a1 writeback -
// grid: (16 t-tiles, 32 bh), block 256, 4x4/thread, TM=64 TN=64 TK=32
__global__ __launch_bounds__(256) void k_av(float* __restrict__ E1)
{
    __shared__ float Ws[32][65];
    __shared__ float Vs[32][65];

    const int bh = blockIdx.y;
    const int b = bh >> 4, h = bh & 15;
    const int t0 = blockIdx.x * 64;

    const float c1 = (float)((double)TT / g_sums[bh]);
    const float c2 = (float)((double)TT / g_sums[32 + bh]);
    const float c3 = (float)((double)TT / g_sums[64 + bh]);
    const float third = 1.0f / 3.0f;

    float* E1p = E1 + (size_t)bh * TT * TT;
    const float* E2p = g_E2 + (size_t)bh * TT * TT;
    const float* E3p = g_E3 + (size_t)bh * TT * TT;
    const float* Vp  = g_P[4] + (size_t)b * TT * EE + h * HD;

    const int tid = threadIdx.x;
    const int tx = tid & 15, ty = tid >> 4;

    float acc[4][4] = {};
    for (int s0 = 0; s0 < TT; s0 += 32) {
#pragma unroll
        for (int e = 0; e < 8; e++) {
            int lin = tid + e * 256;              // 0..2047
            // weight tile: 64 t x 32 s
            int t_l = lin >> 5, s_l = lin & 31;
            size_t ei = (size_t)(t0 + t_l) * TT + s0 + s_l;
            float e1 = E1p[ei];
            float e2 = E2p[ei];
            float e3 = E3p[ei];
            float a1v = e1 * c1;
            E1p[ei] = a1v;                        // scaled a1 -> d_out (in place)
            Ws[s_l][t_l] = (a1v + e2 * c2 + e3 * c3) * third;
            // V tile: 32 s x 64 d
            int s_v = lin >> 6, d_v = lin & 63;
            Vs[s_v][d_v] = Vp[(size_t)(s0 + s_v) * EE + d_v];
        }
        __syncthreads();
#pragma unroll
        for (int kk = 0; kk < 32; kk++) {
            float a[4], bb[4];
#pragma unroll
            for (int i = 0; i < 4; i++) a[i] = Ws[kk][ty + 16 * i];
#pragma unroll
            for (int j = 0; j < 4; j++) bb[j] = Vs[kk][tx + 16 * j];
#pragma unroll
            for (int i = 0; i < 4; i++)
#pragma unroll
                for (int j = 0; j < 4; j++)
                    acc[i][j] = fmaf(a[i], bb[j], acc[i][j]);
        }
        __syncthreads();
    }
#pragma unroll
    for (int i = 0; i < 4; i++) {
        int trow = t0 + ty + 16 * i;
#pragma unroll
        for (int j = 0; j < 4; j++) {
            g_AO[(size_t)(b * TT + trow) * EE + h * HD + tx + 16 * j] = acc[i][j];
        }
    }
}

// ---------------- launch ------------------------------------------------
extern "C" void kernel_launch(void* const* d_in, const int* in_sizes, int n_in,
                              void* d_out, int out_size)
{
    const float* q1  = (const float*)d_in[0];
    const float* q2  = (const float*)d_in[1];
    const float* key = (const float*)d_in[2];
    const float* val = (const float*)d_in[3];
    const float* Wq  = (const float*)d_in[4];
    const float* bq  = (const float*)d_in[5];
    const float* Wq2 = (const float*)d_in[6];
    const float* bq2 = (const float*)d_in[7];
    const float* Wq3 = (const float*)d_in[8];
    const float* bq3 = (const float*)d_in[9];
    const float* Wk  = (const float*)d_in[10];
    const float* bk  = (const float*)d_in[11];
    const float* Wv  = (const float*)d_in[12];
    const float* bv  = (const float*)d_in[13];
    const float* Wo  = (const float*)d_in[14];
    const float* bo  = (const float*)d_in[15];

    float* out = (float*)d_out;                      // [B,T,E]
    float* a1  = out + (size_t)BB * TT * EE;         // [B,H,T,T]

    float* gP;  cudaGetSymbolAddress((void**)&gP, g_P);
    float* gAO; cudaGetSymbolAddress((void**)&gAO, g_AO);

    k_zero_sums<<<1, 128>>>();

    dim3 blk(256);
    dim3 gproj(EE / 128, NTOK / 128);                // (8, 16)

    // projections: q=q1@Wq^T, q2=q2@Wq2^T, q3=key@Wq3^T, k=key@Wk^T, v=val@Wv^T
    const float* Xs[5] = { q1, q2, key, key, val };
    const float* Wsrc[5] = { Wq, Wq2, Wq3, Wk, Wv };
    const float* bs[5] = { bq, bq2, bq3, bk, bv };
    for (int p = 0; p < 5; p++) {
        k_gemm_bias<<<gproj, blk>>>(Xs[p], Wsrc[p], bs[p],
                                    gP + (size_t)p * NTOK * EE,
                                    EE, EE, EE, EE);
    }

    dim3 gscore(TT / 128, TT / 128, 3 * NBH);        // (8, 8, 96)
    k_score<<<gscore, blk>>>(a1);

    dim3 gav(TT / 64, NBH);                          // (16, 32)
    k_av<<<gav, blk>>>(a1);

    dim3 gout(EE / 128, NTOK / 128);                 // (8, 16)
    k_gemm_bias<<<gout, blk>>>(gAO, Wo, bo, out, EE, EE, EE, EE);
}

// round 3
// speedup vs baseline: 2.4215x; 2.4215x over previous
#include <cuda_runtime.h>
#include <cuda_bf16.h>
#include <cstdint>

#define BB 2
#define TT 1024
#define EE 1024
#define HH 16
#define HD 64
#define NTOK (BB*TT)      // 2048
#define NBH  (BB*HH)      // 32
#define ALPHA 0.25f       // (1/sqrt(HD)) / TEMP
#define SK 24             // smem k-stride in bf16 halves (48B rows)

typedef __nv_bfloat16  bf16;
typedef __nv_bfloat162 bf162;

// ---------------- device scratch (no allocation allowed) ----------------
__device__ bf16  g_Xhi[4][(size_t)NTOK * EE], g_Xlo[4][(size_t)NTOK * EE]; // q1,q2,key,value splits
__device__ bf16  g_Whi[6][(size_t)EE * EE],   g_Wlo[6][(size_t)EE * EE];   // Wq,Wq2,Wq3,Wk,Wv,Wo splits
__device__ bf16  g_Qhi[4][(size_t)NTOK * EE], g_Qlo[4][(size_t)NTOK * EE]; // Q1,Q2,Q3,K projections (split)
__device__ float g_V[(size_t)NTOK * EE];                                   // V projection fp32
__device__ float g_E2[(size_t)NBH * TT * TT];                              // exp scores tensor 2
__device__ float g_E3[(size_t)NBH * TT * TT];                              // exp scores tensor 3
__device__ bf16  g_AOhi[(size_t)NTOK * EE], g_AOlo[(size_t)NTOK * EE];     // attn out (split)
__device__ double g_sums[3 * NBH];                                         // softmax denominators

// ---------------- mma helper --------------------------------------------
__device__ __forceinline__ void mma16816(float4& d, const uint32_t* a, const uint32_t* b) {
    asm volatile(
        "mma.sync.aligned.m16n8k16.row.col.f32.bf16.bf16.f32 "
        "{%0,%1,%2,%3}, {%4,%5,%6,%7}, {%8,%9}, {%0,%1,%2,%3};\n"
        : "+f"(d.x), "+f"(d.y), "+f"(d.z), "+f"(d.w)
        : "r"(a[0]), "r"(a[1]), "r"(a[2]), "r"(a[3]),
          "r"(b[0]), "r"(b[1]));
}

__device__ __forceinline__ void split1(float v, bf16& h, bf16& l) {
    h = __float2bfloat16_rn(v);
    l = __float2bfloat16_rn(v - __bfloat162float(h));
}

// ---------------- zero softmax sums -------------------------------------
__global__ void k_zero_sums() {
    int i = threadIdx.x;
    if (i < 3 * NBH) g_sums[i] = 0.0;
}

// ---------------- fp32 -> bf16 hi/lo split ------------------------------
struct SplitArgs { const float* src[6]; bf16* hi[6]; bf16* lo[6]; };

__global__ __launch_bounds__(256) void k_split(SplitArgs a, int n4) {
    const int z = blockIdx.y;
    const int i = blockIdx.x * 256 + threadIdx.x;
    if (i >= n4) return;
    float4 v = ((const float4*)a.src[z])[i];
    bf16 h0, l0, h1, l1, h2, l2, h3, l3;
    split1(v.x, h0, l0); split1(v.y, h1, l1);
    split1(v.z, h2, l2); split1(v.w, h3, l3);
    bf162* hp = (bf162*)a.hi[z];
    bf162* lp = (bf162*)a.lo[z];
    hp[i * 2]     = __halves2bfloat162(h0, h1);
    hp[i * 2 + 1] = __halves2bfloat162(h2, h3);
    lp[i * 2]     = __halves2bfloat162(l0, l1);
    lp[i * 2 + 1] = __halves2bfloat162(l2, l3);
}

// ---------------- bf16x3 GEMM + bias, split or fp32 output --------------
// C[M,N] = A[M,K] * W[N,K]^T + bias, K = EE. grid (N/128, M/128, batch).
struct GArg {
    const bf16 *Ahi, *Alo, *Whi, *Wlo;
    const float* bias;
    bf16 *Chi, *Clo;   // split-output mode if Cf == nullptr
    float* Cf;         // fp32-output mode
};
struct GArgs { GArg g[5]; };

__global__ __launch_bounds__(256) void k_gemm_x3(GArgs args) {
    const GArg ga = args.g[blockIdx.z];
    __shared__ bf16 sA[2][128 * SK];
    __shared__ bf16 sB[2][128 * SK];

    const int tid = threadIdx.x;
    const int lane = tid & 31, warp = tid >> 5;
    const int wm = warp >> 2, wn = warp & 3;
    const int m0 = blockIdx.y * 128, n0 = blockIdx.x * 128;

    const int lr = tid >> 1, hf = tid & 1;
    const bf16* pAh = ga.Ahi + (size_t)(m0 + lr) * EE + hf * 8;
    const bf16* pAl = ga.Alo + (size_t)(m0 + lr) * EE + hf * 8;
    const bf16* pBh = ga.Whi + (size_t)(n0 + lr) * EE + hf * 8;
    const bf16* pBl = ga.Wlo + (size_t)(n0 + lr) * EE + hf * 8;

    float4 acc[4][4];
#pragma unroll
    for (int i = 0; i < 4; i++)
#pragma unroll
        for (int j = 0; j < 4; j++) acc[i][j] = make_float4(0.f, 0.f, 0.f, 0.f);

    uint4 rAh = *(const uint4*)pAh;
    uint4 rAl = *(const uint4*)pAl;
    uint4 rBh = *(const uint4*)pBh;
    uint4 rBl = *(const uint4*)pBl;

    const int r4 = lane >> 2, q2 = (lane & 3) * 2;
    const int soff = lr * SK + hf * 8;

    for (int kc = 0; kc < EE / 16; kc++) {
        *(uint4*)&sA[0][soff] = rAh;
        *(uint4*)&sA[1][soff] = rAl;
        *(uint4*)&sB[0][soff] = rBh;
        *(uint4*)&sB[1][soff] = rBl;
        __syncthreads();
        if (kc + 1 < EE / 16) {
            const int ko = (kc + 1) * 16;
            rAh = *(const uint4*)(pAh + ko);
            rAl = *(const uint4*)(pAl + ko);
            rBh = *(const uint4*)(pBh + ko);
            rBl = *(const uint4*)(pBl + ko);
        }
        uint32_t ah[4][4], al[4][4], bh[4][2], bl[4][2];
#pragma unroll
        for (int mt = 0; mt < 4; mt++) {
            const int m = wm * 64 + mt * 16 + r4;
            ah[mt][0] = *(const uint32_t*)&sA[0][m * SK + q2];
            ah[mt][1] = *(const uint32_t*)&sA[0][(m + 8) * SK + q2];
            ah[mt][2] = *(const uint32_t*)&sA[0][m * SK + q2 + 8];
            ah[mt][3] = *(const uint32_t*)&sA[0][(m + 8) * SK + q2 + 8];
            al[mt][0] = *(const uint32_t*)&sA[1][m * SK + q2];
            al[mt][1] = *(const uint32_t*)&sA[1][(m + 8) * SK + q2];
            al[mt][2] = *(const uint32_t*)&sA[1][m * SK + q2 + 8];
            al[mt][3] = *(const uint32_t*)&sA[1][(m + 8) * SK + q2 + 8];
        }
#pragma unroll
        for (int nt = 0; nt < 4; nt++) {
            const int n = wn * 32 + nt * 8 + r4;
            bh[nt][0] = *(const uint32_t*)&sB[0][n * SK + q2];
            bh[nt][1] = *(const uint32_t*)&sB[0][n * SK + q2 + 8];
            bl[nt][0] = *(const uint32_t*)&sB[1][n * SK + q2];
            bl[nt][1] = *(const uint32_t*)&sB[1][n * SK + q2 + 8];
        }
#pragma unroll
        for (int mt = 0; mt < 4; mt++)
#pragma unroll
            for (int nt = 0; nt < 4; nt++) {
                mma16816(acc[mt][nt], ah[mt], bh[nt]);
                mma16816(acc[mt][nt], ah[mt], bl[nt]);
                mma16816(acc[mt][nt], al[mt], bh[nt]);
            }
        __syncthreads();
    }

#pragma unroll
    for (int mt = 0; mt < 4; mt++) {
        const int row = m0 + wm * 64 + mt * 16 + r4;
#pragma unroll
        for (int nt = 0; nt < 4; nt++) {
            const int col = n0 + wn * 32 + nt * 8 + q2;
            const float bx = ga.bias[col], by = ga.bias[col + 1];
            const float vx = acc[mt][nt].x + bx, vy = acc[mt][nt].y + by;
            const float vz = acc[mt][nt].z + bx, vw = acc[mt][nt].w + by;
            if (ga.Cf) {
                *(float2*)&ga.Cf[(size_t)row * EE + col]       = make_float2(vx, vy);
                *(float2*)&ga.Cf[(size_t)(row + 8) * EE + col] = make_float2(vz, vw);
            } else {
                bf16 h0, l0, h1, l1;
                split1(vx, h0, l0); split1(vy, h1, l1);
                *(bf162*)&ga.Chi[(size_t)row * EE + col] = __halves2bfloat162(h0, h1);
                *(bf162*)&ga.Clo[(size_t)row * EE + col] = __halves2bfloat162(l0, l1);
                split1(vz, h0, l0); split1(vw, h1, l1);
                *(bf162*)&ga.Chi[(size_t)(row + 8) * EE + col] = __halves2bfloat162(h0, h1);
                *(bf162*)&ga.Clo[(size_t)(row + 8) * EE + col] = __halves2bfloat162(l0, l1);
            }
        }
    }
}

// ---------------- scores: exp((Qh Kh^T)*ALPHA) bf16x3, fused global sum --
// grid (8, 8, 96): z = tensor*32 + bh
__global__ __launch_bounds__(256) void k_score(float* __restrict__ E1out) {
    __shared__ bf16 sA[2][128 * SK];
    __shared__ bf16 sB[2][128 * SK];
    __shared__ float red[256];

    const int zz = blockIdx.z;
    const int tensor = zz >> 5, bh = zz & 31;
    const int b = bh >> 4, h = bh & 15;
    const size_t hofs = (size_t)b * TT * EE + h * HD;

    const bf16* Qh = g_Qhi[tensor] + hofs;
    const bf16* Ql = g_Qlo[tensor] + hofs;
    const bf16* Kh = g_Qhi[3] + hofs;
    const bf16* Kl = g_Qlo[3] + hofs;
    float* Eo = (tensor == 0) ? E1out : (tensor == 1 ? g_E2 : g_E3);
    Eo += (size_t)bh * TT * TT;

    const int tid = threadIdx.x;
    const int lane = tid & 31, warp = tid >> 5;
    const int wm = warp >> 2, wn = warp & 3;
    const int m0 = blockIdx.y * 128, n0 = blockIdx.x * 128;

    const int lr = tid >> 1, hf = tid & 1;
    const bf16* pAh = Qh + (size_t)(m0 + lr) * EE + hf * 8;
    const bf16* pAl = Ql + (size_t)(m0 + lr) * EE + hf * 8;
    const bf16* pBh = Kh + (size_t)(n0 + lr) * EE + hf * 8;
    const bf16* pBl = Kl + (size_t)(n0 + lr) * EE + hf * 8;

    float4 acc[4][4];
#pragma unroll
    for (int i = 0; i < 4; i++)
#pragma unroll
        for (int j = 0; j < 4; j++) acc[i][j] = make_float4(0.f, 0.f, 0.f, 0.f);

    uint4 rAh = *(const uint4*)pAh;
    uint4 rAl = *(const uint4*)pAl;
    uint4 rBh = *(const uint4*)pBh;
    uint4 rBl = *(const uint4*)pBl;

    const int r4 = lane >> 2, q2 = (lane & 3) * 2;
    const int soff = lr * SK + hf * 8;

#pragma unroll
    for (int kc = 0; kc < HD / 16; kc++) {
        *(uint4*)&sA[0][soff] = rAh;
        *(uint4*)&sA[1][soff] = rAl;
        *(uint4*)&sB[0][soff] = rBh;
        *(uint4*)&sB[1][soff] = rBl;
        __syncthreads();
        if (kc + 1 < HD / 16) {
            const int ko = (kc + 1) * 16;
            rAh = *(const uint4*)(pAh + ko);
            rAl = *(const uint4*)(pAl + ko);
            rBh = *(const uint4*)(pBh + ko);
            rBl = *(const uint4*)(pBl + ko);
        }
        uint32_t ah[4][4], al[4][4], bh[4][2], bl[4][2];
#pragma unroll
        for (int mt = 0; mt < 4; mt++) {
            const int m = wm * 64 + mt * 16 + r4;
            ah[mt][0] = *(const uint32_t*)&sA[0][m * SK + q2];
            ah[mt][1] = *(const uint32_t*)&sA[0][(m + 8) * SK + q2];
            ah[mt][2] = *(const uint32_t*)&sA[0][m * SK + q2 + 8];
            ah[mt][3] = *(const uint32_t*)&sA[0][(m + 8) * SK + q2 + 8];
            al[mt][0] = *(const uint32_t*)&sA[1][m * SK + q2];
            al[mt][1] = *(const uint32_t*)&sA[1][(m + 8) * SK + q2];
            al[mt][2] = *(const uint32_t*)&sA[1][m * SK + q2 + 8];
            al[mt][3] = *(const uint32_t*)&sA[1][(m + 8) * SK + q2 + 8];
        }
#pragma unroll
        for (int nt = 0; nt < 4; nt++) {
            const int n = wn * 32 + nt * 8 + r4;
            bh[nt][0] = *(const uint32_t*)&sB[0][n * SK + q2];
            bh[nt][1] = *(const uint32_t*)&sB[0][n * SK + q2 + 8];
            bl[nt][0] = *(const uint32_t*)&sB[1][n * SK + q2];
            bl[nt][1] = *(const uint32_t*)&sB[1][n * SK + q2 + 8];
        }
#pragma unroll
        for (int mt = 0; mt < 4; mt++)
#pragma unroll
            for (int nt = 0; nt < 4; nt++) {
                mma16816(acc[mt][nt], ah[mt], bh[nt]);
                mma16816(acc[mt][nt], ah[mt], bl[nt]);
                mma16816(acc[mt][nt], al[mt], bh[nt]);
            }
        __syncthreads();
    }

    float lsum = 0.f;
#pragma unroll
    for (int mt = 0; mt < 4; mt++) {
        const int row = m0 + wm * 64 + mt * 16 + r4;
#pragma unroll
        for (int nt = 0; nt < 4; nt++) {
            const int col = n0 + wn * 32 + nt * 8 + q2;
            const float vx = __expf(acc[mt][nt].x * ALPHA);
            const float vy = __expf(acc[mt][nt].y * ALPHA);
            const float vz = __expf(acc[mt][nt].z * ALPHA);
            const float vw = __expf(acc[mt][nt].w * ALPHA);
            *(float2*)&Eo[(size_t)row * TT + col]       = make_float2(vx, vy);
            *(float2*)&Eo[(size_t)(row + 8) * TT + col] = make_float2(vz, vw);
            lsum += vx + vy + vz + vw;
        }
    }
    red[tid] = lsum;
    __syncthreads();
    for (int s = 128; s > 0; s >>= 1) {
        if (tid < s) red[tid] += red[tid + s];
        __syncthreads();
    }
    if (tid == 0) atomicAdd(&g_sums[zz], (double)red[0]);
}

// ---------------- AV: attn_out = ((a1+a2+a3)/3) @ V ----------------------
// fused a1 writeback + bf16 split of AO. grid (16, 32), block 256.
__global__ __launch_bounds__(256) void k_av(float* __restrict__ E1) {
    __shared__ float Ws[32][68];
    __shared__ float Vs[32][68];

    const int bh = blockIdx.y;
    const int b = bh >> 4, h = bh & 15;
    const int t0 = blockIdx.x * 64;

    const float c1 = (float)((double)TT / g_sums[bh]);
    const float c2 = (float)((double)TT / g_sums[32 + bh]);
    const float c3 = (float)((double)TT / g_sums[64 + bh]);
    const float third = 1.0f / 3.0f;

    float* E1p = E1 + (size_t)bh * TT * TT;
    const float* E2p = g_E2 + (size_t)bh * TT * TT;
    const float* E3p = g_E3 + (size_t)bh * TT * TT;
    const float* Vp  = g_V + (size_t)b * TT * EE + h * HD;

    const int tid = threadIdx.x;
    const int tx = tid & 15, ty = tid >> 4;

    float acc[4][4] = {};
    for (int s0 = 0; s0 < TT; s0 += 32) {
#pragma unroll
        for (int e = 0; e < 2; e++) {
            const int lin = tid + e * 256;             // 0..511
            const int t_l = lin >> 3, sq = lin & 7;    // 64 t x 8 s-quads
            const size_t ei = (size_t)(t0 + t_l) * TT + s0 + sq * 4;
            float4 e1 = *(float4*)&E1p[ei];
            float4 e2 = *(const float4*)&E2p[ei];
            float4 e3 = *(const float4*)&E3p[ei];
            float4 a1v = make_float4(e1.x * c1, e1.y * c1, e1.z * c1, e1.w * c1);
            *(float4*)&E1p[ei] = a1v;                  // scaled a1 -> d_out
            Ws[sq * 4 + 0][t_l] = (a1v.x + e2.x * c2 + e3.x * c3) * third;
            Ws[sq * 4 + 1][t_l] = (a1v.y + e2.y * c2 + e3.y * c3) * third;
            Ws[sq * 4 + 2][t_l] = (a1v.z + e2.z * c2 + e3.z * c3) * third;
            Ws[sq * 4 + 3][t_l] = (a1v.w + e2.w * c2 + e3.w * c3) * third;
            const int s_v = lin >> 4, dq = lin & 15;   // 32 s x 16 d-quads
            *(float4*)&Vs[s_v][dq * 4] = *(const float4*)&Vp[(size_t)(s0 + s_v) * EE + dq * 4];
        }
        __syncthreads();
#pragma unroll
        for (int kk = 0; kk < 32; kk++) {
            const float4 a = *(float4*)&Ws[kk][ty * 4];
            const float4 v = *(float4*)&Vs[kk][tx * 4];
            const float av[4] = { a.x, a.y, a.z, a.w };
            const float bv[4] = { v.x, v.y, v.z, v.w };
#pragma unroll
            for (int i = 0; i < 4; i++)
#pragma unroll
                for (int j = 0; j < 4; j++)
                    acc[i][j] = fmaf(av[i], bv[j], acc[i][j]);
        }
        __syncthreads();
    }
#pragma unroll
    for (int i = 0; i < 4; i++) {
        const size_t base = (size_t)(b * TT + t0 + ty * 4 + i) * EE + h * HD + tx * 4;
        bf16 h0, l0, h1, l1;
        split1(acc[i][0], h0, l0); split1(acc[i][1], h1, l1);
        *(bf162*)&g_AOhi[base] = __halves2bfloat162(h0, h1);
        *(bf162*)&g_AOlo[base] = __halves2bfloat162(l0, l1);
        split1(acc[i][2], h0, l0); split1(acc[i][3], h1, l1);
        *(bf162*)&g_AOhi[base + 2] = __halves2bfloat162(h0, h1);
        *(bf162*)&g_AOlo[base + 2] = __halves2bfloat162(l0, l1);
    }
}

// ---------------- launch ------------------------------------------------
extern "C" void kernel_launch(void* const* d_in, const int* in_sizes, int n_in,
                              void* d_out, int out_size)
{
    const float* q1  = (const float*)d_in[0];
    const float* q2  = (const float*)d_in[1];
    const float* key = (const float*)d_in[2];
    const float* val = (const float*)d_in[3];
    const float* Wq  = (const float*)d_in[4];
    const float* bq  = (const float*)d_in[5];
    const float* Wq2 = (const float*)d_in[6];
    const float* bq2 = (const float*)d_in[7];
    const float* Wq3 = (const float*)d_in[8];
    const float* bq3 = (const float*)d_in[9];
    const float* Wk  = (const float*)d_in[10];
    const float* bk  = (const float*)d_in[11];
    const float* Wv  = (const float*)d_in[12];
    const float* bv  = (const float*)d_in[13];
    const float* Wo  = (const float*)d_in[14];
    const float* bo  = (const float*)d_in[15];

    float* out = (float*)d_out;                      // [B,T,E]
    float* a1  = out + (size_t)BB * TT * EE;         // [B,H,T,T]

    bf16 *Xhi, *Xlo, *Whi, *Wlo, *Qhi, *Qlo, *AOhi, *AOlo;
    float* V;
    cudaGetSymbolAddress((void**)&Xhi, g_Xhi);
    cudaGetSymbolAddress((void**)&Xlo, g_Xlo);
    cudaGetSymbolAddress((void**)&Whi, g_Whi);
    cudaGetSymbolAddress((void**)&Wlo, g_Wlo);
    cudaGetSymbolAddress((void**)&Qhi, g_Qhi);
    cudaGetSymbolAddress((void**)&Qlo, g_Qlo);
    cudaGetSymbolAddress((void**)&AOhi, g_AOhi);
    cudaGetSymbolAddress((void**)&AOlo, g_AOlo);
    cudaGetSymbolAddress((void**)&V, g_V);

    k_zero_sums<<<1, 128>>>();

    // splits
    SplitArgs si = {};
    const float* xs[4] = { q1, q2, key, val };
    for (int i = 0; i < 4; i++) {
        si.src[i] = xs[i];
        si.hi[i] = Xhi + (size_t)i * NTOK * EE;
        si.lo[i] = Xlo + (size_t)i * NTOK * EE;
    }
    k_split<<<dim3((NTOK * EE / 4) / 256, 4), 256>>>(si, NTOK * EE / 4);

    SplitArgs sw = {};
    const float* ws[6] = { Wq, Wq2, Wq3, Wk, Wv, Wo };
    for (int i = 0; i < 6; i++) {
        sw.src[i] = ws[i];
        sw.hi[i] = Whi + (size_t)i * EE * EE;
        sw.lo[i] = Wlo + (size_t)i * EE * EE;
    }
    k_split<<<dim3((EE * EE / 4) / 256, 6), 256>>>(sw, EE * EE / 4);

    // projections: Q1,Q2,Q3,K (split out) + V (fp32 out) in one launch
    GArgs pa = {};
    const int aidx[5] = { 0, 1, 2, 2, 3 };           // q1, q2, key, key, value
    const float* bs[5] = { bq, bq2, bq3, bk, bv };
    for (int p = 0; p < 5; p++) {
        pa.g[p].Ahi = Xhi + (size_t)aidx[p] * NTOK * EE;
        pa.g[p].Alo = Xlo + (size_t)aidx[p] * NTOK * EE;
        pa.g[p].Whi = Whi + (size_t)p * EE * EE;
        pa.g[p].Wlo = Wlo + (size_t)p * EE * EE;
        pa.g[p].bias = bs[p];
        if (p < 4) {
            pa.g[p].Chi = Qhi + (size_t)p * NTOK * EE;
            pa.g[p].Clo = Qlo + (size_t)p * NTOK * EE;
            pa.g[p].Cf = nullptr;
        } else {
            pa.g[p].Chi = nullptr; pa.g[p].Clo = nullptr;
            pa.g[p].Cf = V;
        }
    }
    k_gemm_x3<<<dim3(EE / 128, NTOK / 128, 5), 256>>>(pa);

    k_score<<<dim3(TT / 128, TT / 128, 3 * NBH), 256>>>(a1);

    k_av<<<dim3(TT / 64, NBH), 256>>>(a1);

    GArgs fo = {};
    fo.g[0].Ahi = AOhi; fo.g[0].Alo = AOlo;
    fo.g[0].Whi = Whi + (size_t)5 * EE * EE;
    fo.g[0].Wlo = Wlo + (size_t)5 * EE * EE;
    fo.g[0].bias = bo;
    fo.g[0].Chi = nullptr; fo.g[0].Clo = nullptr;
    fo.g[0].Cf = out;
    k_gemm_x3<<<dim3(EE / 128, NTOK / 128, 1), 256>>>(fo);
}

// round 4
// speedup vs baseline: 2.7604x; 1.1399x over previous
#include <cuda_runtime.h>
#include <cuda_bf16.h>
#include <cstdint>

#define BB 2
#define TT 1024
#define EE 1024
#define HH 16
#define HD 64
#define NTOK (BB*TT)      // 2048
#define NBH  (BB*HH)      // 32
#define ALPHA 0.25f       // (1/sqrt(HD)) / TEMP

typedef __nv_bfloat16  bf16;
typedef __nv_bfloat162 bf162;

// ---------------- device scratch (no allocation allowed) ----------------
__device__ bf16  g_Xhi[4][(size_t)NTOK * EE], g_Xlo[4][(size_t)NTOK * EE]; // q1,q2,key,value splits
__device__ bf16  g_Whi[6][(size_t)EE * EE],   g_Wlo[6][(size_t)EE * EE];   // weight splits
__device__ bf16  g_Qhi[4][(size_t)NTOK * EE], g_Qlo[4][(size_t)NTOK * EE]; // Q1,Q2,Q3,K projections (split)
__device__ float g_V[(size_t)NTOK * EE];                                   // V projection fp32
__device__ float g_E2[(size_t)NBH * TT * TT];                              // exp scores tensor 2
__device__ float g_E3[(size_t)NBH * TT * TT];                              // exp scores tensor 3
__device__ bf16  g_AOhi[(size_t)NTOK * EE], g_AOlo[(size_t)NTOK * EE];     // attn out (split)
__device__ double g_sums[3 * NBH];                                         // softmax denominators

// ---------------- low-level helpers -------------------------------------
__device__ __forceinline__ uint32_t s2u(const void* p) {
    return (uint32_t)__cvta_generic_to_shared(p);
}
__device__ __forceinline__ void cpasync16(uint32_t s, const void* g) {
    asm volatile("cp.async.cg.shared.global [%0], [%1], 16;\n" :: "r"(s), "l"(g));
}
#define CP_COMMIT asm volatile("cp.async.commit_group;\n")
#define CP_WAIT1  asm volatile("cp.async.wait_group 1;\n")
#define CP_WAIT0  asm volatile("cp.async.wait_group 0;\n")

__device__ __forceinline__ void ldsm4(uint32_t a, uint32_t& r0, uint32_t& r1, uint32_t& r2, uint32_t& r3) {
    asm volatile("ldmatrix.sync.aligned.m8n8.x4.shared.b16 {%0,%1,%2,%3}, [%4];\n"
                 : "=r"(r0), "=r"(r1), "=r"(r2), "=r"(r3) : "r"(a));
}
__device__ __forceinline__ void ldsm4t(uint32_t a, uint32_t& r0, uint32_t& r1, uint32_t& r2, uint32_t& r3) {
    asm volatile("ldmatrix.sync.aligned.m8n8.x4.trans.shared.b16 {%0,%1,%2,%3}, [%4];\n"
                 : "=r"(r0), "=r"(r1), "=r"(r2), "=r"(r3) : "r"(a));
}
__device__ __forceinline__ void mma16816(float4& d, const uint32_t* a, const uint32_t* b) {
    asm volatile(
        "mma.sync.aligned.m16n8k16.row.col.f32.bf16.bf16.f32 "
        "{%0,%1,%2,%3}, {%4,%5,%6,%7}, {%8,%9}, {%0,%1,%2,%3};\n"
        : "+f"(d.x), "+f"(d.y), "+f"(d.z), "+f"(d.w)
        : "r"(a[0]), "r"(a[1]), "r"(a[2]), "r"(a[3]),
          "r"(b[0]), "r"(b[1]));
}
__device__ __forceinline__ void split1(float v, bf16& h, bf16& l) {
    h = __float2bfloat16_rn(v);
    l = __float2bfloat16_rn(v - __bfloat162float(h));
}

// ---------------- shared mma block: one k16 step -------------------------
// A tiles at sAh/sAl (row-major, stride SKH halves), B at sBh/sBl.
// warp tile 64m x 32n (wm in 0..1, wn in 0..3). acc[4][4].
template<int SKH>
__device__ __forceinline__ void mma_block16(
    const bf16* sAh, const bf16* sAl, const bf16* sBh, const bf16* sBl,
    int ko, int wm, int wn, int lane, float4 acc[4][4])
{
    uint32_t ah[4][4], al[4][4], bh[4][2], bl[4][2];
    const int arow = wm * 64 + (lane & 15);
    const int ak = ko + (lane >> 4) * 8;
#pragma unroll
    for (int mt = 0; mt < 4; mt++) {
        ldsm4(s2u(sAh + (arow + mt * 16) * SKH + ak), ah[mt][0], ah[mt][1], ah[mt][2], ah[mt][3]);
        ldsm4(s2u(sAl + (arow + mt * 16) * SKH + ak), al[mt][0], al[mt][1], al[mt][2], al[mt][3]);
    }
    const int brow = wn * 32 + ((lane >> 4) & 1) * 8 + (lane & 7);
    const int bk = ko + ((lane >> 3) & 1) * 8;
#pragma unroll
    for (int p2 = 0; p2 < 2; p2++) {
        uint32_t r0, r1, r2, r3;
        ldsm4(s2u(sBh + (brow + p2 * 16) * SKH + bk), r0, r1, r2, r3);
        bh[p2 * 2][0] = r0; bh[p2 * 2][1] = r1; bh[p2 * 2 + 1][0] = r2; bh[p2 * 2 + 1][1] = r3;
        ldsm4(s2u(sBl + (brow + p2 * 16) * SKH + bk), r0, r1, r2, r3);
        bl[p2 * 2][0] = r0; bl[p2 * 2][1] = r1; bl[p2 * 2 + 1][0] = r2; bl[p2 * 2 + 1][1] = r3;
    }
#pragma unroll
    for (int mt = 0; mt < 4; mt++)
#pragma unroll
        for (int nt = 0; nt < 4; nt++) {
            mma16816(acc[mt][nt], ah[mt], bh[nt]);
            mma16816(acc[mt][nt], ah[mt], bl[nt]);
            mma16816(acc[mt][nt], al[mt], bh[nt]);
        }
}

// ---------------- zero softmax sums -------------------------------------
__global__ void k_zero_sums() {
    int i = threadIdx.x;
    if (i < 3 * NBH) g_sums[i] = 0.0;
}

// ---------------- fp32 -> bf16 hi/lo split ------------------------------
struct SplitArgs { const float* src[6]; bf16* hi[6]; bf16* lo[6]; };

__global__ __launch_bounds__(256) void k_split(SplitArgs a, int n4) {
    const int z = blockIdx.y;
    const int i = blockIdx.x * 256 + threadIdx.x;
    if (i >= n4) return;
    float4 v = ((const float4*)a.src[z])[i];
    bf16 h0, l0, h1, l1, h2, l2, h3, l3;
    split1(v.x, h0, l0); split1(v.y, h1, l1);
    split1(v.z, h2, l2); split1(v.w, h3, l3);
    bf162* hp = (bf162*)a.hi[z];
    bf162* lp = (bf162*)a.lo[z];
    hp[i * 2]     = __halves2bfloat162(h0, h1);
    hp[i * 2 + 1] = __halves2bfloat162(h2, h3);
    lp[i * 2]     = __halves2bfloat162(l0, l1);
    lp[i * 2 + 1] = __halves2bfloat162(l2, l3);
}

// ---------------- bf16x3 GEMM + bias, cp.async 2-stage, ldmatrix --------
// C[M,N] = A[M,K] * W[N,K]^T + bias, K = EE. grid (N/128, M/128, batch).
struct GArg {
    const bf16 *Ahi, *Alo, *Whi, *Wlo;
    const float* bias;
    bf16 *Chi, *Clo;   // split-output mode if Cf == nullptr
    float* Cf;         // fp32-output mode
};
struct GArgs { GArg g[5]; };

#define GEMM_SKH 40
#define GEMM_SPL (128 * GEMM_SKH)
#define GEMM_STG (4 * GEMM_SPL)
#define GEMM_SMEM (2 * GEMM_STG * 2)   // bytes

__global__ __launch_bounds__(256) void k_gemm_x3(GArgs args) {
    extern __shared__ __align__(16) bf16 sm[];
    const GArg ga = args.g[blockIdx.z];

    const int tid = threadIdx.x;
    const int lane = tid & 31, warp = tid >> 5;
    const int wm = warp >> 2, wn = warp & 3;
    const int m0 = blockIdx.y * 128, n0 = blockIdx.x * 128;

    const int r = tid & 127, c0 = tid >> 7;
    const bf16* gp[4] = {
        ga.Ahi + (size_t)(m0 + r) * EE,
        ga.Alo + (size_t)(m0 + r) * EE,
        ga.Whi + (size_t)(n0 + r) * EE,
        ga.Wlo + (size_t)(n0 + r) * EE
    };
    const uint32_t sbase = s2u(sm);

    auto issue = [&](int kc, int p) {
#pragma unroll
        for (int mat = 0; mat < 4; mat++)
#pragma unroll
            for (int e = 0; e < 2; e++) {
                const int cc = c0 + 2 * e;
                uint32_t sa = sbase + (uint32_t)(p * GEMM_STG + mat * GEMM_SPL + r * GEMM_SKH + cc * 8) * 2;
                cpasync16(sa, gp[mat] + kc * 32 + cc * 8);
            }
    };
    issue(0, 0); CP_COMMIT;
    issue(1, 1); CP_COMMIT;

    float4 acc[4][4];
#pragma unroll
    for (int i = 0; i < 4; i++)
#pragma unroll
        for (int j = 0; j < 4; j++) acc[i][j] = make_float4(0.f, 0.f, 0.f, 0.f);

    for (int kc = 0; kc < EE / 32; kc++) {
        CP_WAIT1;
        __syncthreads();
        const int p = kc & 1;
        const bf16* sAh = sm + p * GEMM_STG;
        const bf16* sAl = sAh + GEMM_SPL;
        const bf16* sBh = sAl + GEMM_SPL;
        const bf16* sBl = sBh + GEMM_SPL;
        mma_block16<GEMM_SKH>(sAh, sAl, sBh, sBl, 0,  wm, wn, lane, acc);
        mma_block16<GEMM_SKH>(sAh, sAl, sBh, sBl, 16, wm, wn, lane, acc);
        __syncthreads();
        if (kc + 2 < EE / 32) issue(kc + 2, p);
        CP_COMMIT;
    }

    const int r4 = lane >> 2, q2 = (lane & 3) * 2;
#pragma unroll
    for (int mt = 0; mt < 4; mt++) {
        const int row = m0 + wm * 64 + mt * 16 + r4;
#pragma unroll
        for (int nt = 0; nt < 4; nt++) {
            const int col = n0 + wn * 32 + nt * 8 + q2;
            const float bx = ga.bias[col], by = ga.bias[col + 1];
            const float vx = acc[mt][nt].x + bx, vy = acc[mt][nt].y + by;
            const float vz = acc[mt][nt].z + bx, vw = acc[mt][nt].w + by;
            if (ga.Cf) {
                *(float2*)&ga.Cf[(size_t)row * EE + col]       = make_float2(vx, vy);
                *(float2*)&ga.Cf[(size_t)(row + 8) * EE + col] = make_float2(vz, vw);
            } else {
                bf16 h0, l0, h1, l1;
                split1(vx, h0, l0); split1(vy, h1, l1);
                *(bf162*)&ga.Chi[(size_t)row * EE + col] = __halves2bfloat162(h0, h1);
                *(bf162*)&ga.Clo[(size_t)row * EE + col] = __halves2bfloat162(l0, l1);
                split1(vz, h0, l0); split1(vw, h1, l1);
                *(bf162*)&ga.Chi[(size_t)(row + 8) * EE + col] = __halves2bfloat162(h0, h1);
                *(bf162*)&ga.Clo[(size_t)(row + 8) * EE + col] = __halves2bfloat162(l0, l1);
            }
        }
    }
}

// ---------------- scores: exp((Qh Kh^T)*ALPHA) bf16x3, fused global sum --
// K=64 staged whole via cp.async. grid (8, 8, 96): z = tensor*32 + bh
#define SC_SKH 72
#define SC_SPL (128 * SC_SKH)
#define SC_SMEM (4 * SC_SPL * 2 + 1024)

__global__ __launch_bounds__(256) void k_score(float* __restrict__ E1out) {
    extern __shared__ __align__(16) bf16 sm[];
    float* red = (float*)(sm + 4 * SC_SPL);

    const int zz = blockIdx.z;
    const int tensor = zz >> 5, bh = zz & 31;
    const int b = bh >> 4, h = bh & 15;
    const size_t hofs = (size_t)b * TT * EE + h * HD;

    const bf16* Qh = g_Qhi[tensor] + hofs;
    const bf16* Ql = g_Qlo[tensor] + hofs;
    const bf16* Kh = g_Qhi[3] + hofs;
    const bf16* Kl = g_Qlo[3] + hofs;
    float* Eo = (tensor == 0) ? E1out : (tensor == 1 ? g_E2 : g_E3);
    Eo += (size_t)bh * TT * TT;

    const int tid = threadIdx.x;
    const int lane = tid & 31, warp = tid >> 5;
    const int wm = warp >> 2, wn = warp & 3;
    const int m0 = blockIdx.y * 128, n0 = blockIdx.x * 128;

    const int r = tid & 127, c0 = tid >> 7;
    const bf16* gp[4] = {
        Qh + (size_t)(m0 + r) * EE, Ql + (size_t)(m0 + r) * EE,
        Kh + (size_t)(n0 + r) * EE, Kl + (size_t)(n0 + r) * EE
    };
    const uint32_t sbase = s2u(sm);
#pragma unroll
    for (int mat = 0; mat < 4; mat++)
#pragma unroll
        for (int e = 0; e < 4; e++) {
            const int cc = c0 + 2 * e;
            cpasync16(sbase + (uint32_t)(mat * SC_SPL + r * SC_SKH + cc * 8) * 2, gp[mat] + cc * 8);
        }
    CP_COMMIT; CP_WAIT0;
    __syncthreads();

    float4 acc[4][4];
#pragma unroll
    for (int i = 0; i < 4; i++)
#pragma unroll
        for (int j = 0; j < 4; j++) acc[i][j] = make_float4(0.f, 0.f, 0.f, 0.f);

    const bf16* sAh = sm;
    const bf16* sAl = sAh + SC_SPL;
    const bf16* sBh = sAl + SC_SPL;
    const bf16* sBl = sBh + SC_SPL;
#pragma unroll
    for (int ko = 0; ko < 64; ko += 16)
        mma_block16<SC_SKH>(sAh, sAl, sBh, sBl, ko, wm, wn, lane, acc);

    const int r4 = lane >> 2, q2 = (lane & 3) * 2;
    float lsum = 0.f;
#pragma unroll
    for (int mt = 0; mt < 4; mt++) {
        const int row = m0 + wm * 64 + mt * 16 + r4;
#pragma unroll
        for (int nt = 0; nt < 4; nt++) {
            const int col = n0 + wn * 32 + nt * 8 + q2;
            const float vx = __expf(acc[mt][nt].x * ALPHA);
            const float vy = __expf(acc[mt][nt].y * ALPHA);
            const float vz = __expf(acc[mt][nt].z * ALPHA);
            const float vw = __expf(acc[mt][nt].w * ALPHA);
            *(float2*)&Eo[(size_t)row * TT + col]       = make_float2(vx, vy);
            *(float2*)&Eo[(size_t)(row + 8) * TT + col] = make_float2(vz, vw);
            lsum += vx + vy + vz + vw;
        }
    }
    red[tid] = lsum;
    __syncthreads();
    for (int s = 128; s > 0; s >>= 1) {
        if (tid < s) red[tid] += red[tid + s];
        __syncthreads();
    }
    if (tid == 0) atomicAdd(&g_sums[zz], (double)red[0]);
}

// ---------------- AV: ((a1+a2+a3)/3) @ V, tensorized bf16x3 --------------
// grid (TT/128, NBH). Fused a1 scale-writeback + AO split output.
__global__ __launch_bounds__(256) void k_av(float* __restrict__ E1) {
    __shared__ bf16 sW[2][128 * 40];   // W hi/lo, [t][s] stride 40
    __shared__ bf16 sV[2][32 * 72];    // V hi/lo, [s][d] stride 72

    const int bh = blockIdx.y;
    const int b = bh >> 4, h = bh & 15;
    const int t0 = blockIdx.x * 128;

    const float c1 = (float)((double)TT / g_sums[bh]);
    const float c2 = (float)((double)TT / g_sums[32 + bh]);
    const float c3 = (float)((double)TT / g_sums[64 + bh]);
    const float third = 1.0f / 3.0f;

    float* E1p = E1 + (size_t)bh * TT * TT;
    const float* E2p = g_E2 + (size_t)bh * TT * TT;
    const float* E3p = g_E3 + (size_t)bh * TT * TT;
    const float* Vp  = g_V + (size_t)b * TT * EE + h * HD;

    const int tid = threadIdx.x;
    const int lane = tid & 31, warp = tid >> 5;
    const int wm = warp >> 2, wn = warp & 3;

    float4 acc[4][2];
#pragma unroll
    for (int i = 0; i < 4; i++)
#pragma unroll
        for (int j = 0; j < 2; j++) acc[i][j] = make_float4(0.f, 0.f, 0.f, 0.f);

    for (int s0 = 0; s0 < TT; s0 += 32) {
#pragma unroll
        for (int e = 0; e < 4; e++) {
            const int lin = tid + e * 256;          // 0..1023
            const int t = lin >> 3, s4 = (lin & 7) * 4;
            const size_t ei = (size_t)(t0 + t) * TT + s0 + s4;
            float4 e1 = *(float4*)&E1p[ei];
            float4 e2 = *(const float4*)&E2p[ei];
            float4 e3 = *(const float4*)&E3p[ei];
            float4 a1v = make_float4(e1.x * c1, e1.y * c1, e1.z * c1, e1.w * c1);
            *(float4*)&E1p[ei] = a1v;               // scaled a1 -> d_out
            const float w0 = (a1v.x + e2.x * c2 + e3.x * c3) * third;
            const float w1 = (a1v.y + e2.y * c2 + e3.y * c3) * third;
            const float w2 = (a1v.z + e2.z * c2 + e3.z * c3) * third;
            const float w3 = (a1v.w + e2.w * c2 + e3.w * c3) * third;
            bf16 h0, l0, h1, l1, h2, l2, h3, l3;
            split1(w0, h0, l0); split1(w1, h1, l1);
            split1(w2, h2, l2); split1(w3, h3, l3);
            *(bf162*)&sW[0][t * 40 + s4]     = __halves2bfloat162(h0, h1);
            *(bf162*)&sW[0][t * 40 + s4 + 2] = __halves2bfloat162(h2, h3);
            *(bf162*)&sW[1][t * 40 + s4]     = __halves2bfloat162(l0, l1);
            *(bf162*)&sW[1][t * 40 + s4 + 2] = __halves2bfloat162(l2, l3);
        }
#pragma unroll
        for (int e = 0; e < 2; e++) {
            const int lin = tid + e * 256;          // 0..511
            const int s = lin >> 4, d4 = (lin & 15) * 4;
            float4 v = *(const float4*)&Vp[(size_t)(s0 + s) * EE + d4];
            bf16 h0, l0, h1, l1, h2, l2, h3, l3;
            split1(v.x, h0, l0); split1(v.y, h1, l1);
            split1(v.z, h2, l2); split1(v.w, h3, l3);
            *(bf162*)&sV[0][s * 72 + d4]     = __halves2bfloat162(h0, h1);
            *(bf162*)&sV[0][s * 72 + d4 + 2] = __halves2bfloat162(h2, h3);
            *(bf162*)&sV[1][s * 72 + d4]     = __halves2bfloat162(l0, l1);
            *(bf162*)&sV[1][s * 72 + d4 + 2] = __halves2bfloat162(l2, l3);
        }
        __syncthreads();
#pragma unroll
        for (int ks = 0; ks < 32; ks += 16) {
            uint32_t ah[4][4], al[4][4], bv[2][2][2];   // bv[sigma][nt][k]
            const int arow = wm * 64 + (lane & 15);
            const int ak = ks + (lane >> 4) * 8;
#pragma unroll
            for (int mt = 0; mt < 4; mt++) {
                ldsm4(s2u(&sW[0][(arow + mt * 16) * 40 + ak]), ah[mt][0], ah[mt][1], ah[mt][2], ah[mt][3]);
                ldsm4(s2u(&sW[1][(arow + mt * 16) * 40 + ak]), al[mt][0], al[mt][1], al[mt][2], al[mt][3]);
            }
            const int srow = ks + ((lane >> 3) & 1) * 8 + (lane & 7);
            const int dcol = wn * 16 + ((lane >> 4) & 1) * 8;
#pragma unroll
            for (int sg = 0; sg < 2; sg++) {
                uint32_t r0, r1, r2, r3;
                ldsm4t(s2u(&sV[sg][srow * 72 + dcol]), r0, r1, r2, r3);
                bv[sg][0][0] = r0; bv[sg][0][1] = r1;
                bv[sg][1][0] = r2; bv[sg][1][1] = r3;
            }
#pragma unroll
            for (int mt = 0; mt < 4; mt++)
#pragma unroll
                for (int nt = 0; nt < 2; nt++) {
                    mma16816(acc[mt][nt], ah[mt], bv[0][nt]);
                    mma16816(acc[mt][nt], ah[mt], bv[1][nt]);
                    mma16816(acc[mt][nt], al[mt], bv[0][nt]);
                }
        }
        __syncthreads();
    }

    const int r4 = lane >> 2, q2 = (lane & 3) * 2;
#pragma unroll
    for (int mt = 0; mt < 4; mt++) {
        const int trow = t0 + wm * 64 + mt * 16 + r4;
#pragma unroll
        for (int nt = 0; nt < 2; nt++) {
            const int col = h * HD + wn * 16 + nt * 8 + q2;
            bf16 h0, l0, h1, l1;
            const size_t base0 = (size_t)(b * TT + trow) * EE + col;
            split1(acc[mt][nt].x, h0, l0); split1(acc[mt][nt].y, h1, l1);
            *(bf162*)&g_AOhi[base0] = __halves2bfloat162(h0, h1);
            *(bf162*)&g_AOlo[base0] = __halves2bfloat162(l0, l1);
            const size_t base1 = (size_t)(b * TT + trow + 8) * EE + col;
            split1(acc[mt][nt].z, h0, l0); split1(acc[mt][nt].w, h1, l1);
            *(bf162*)&g_AOhi[base1] = __halves2bfloat162(h0, h1);
            *(bf162*)&g_AOlo[base1] = __halves2bfloat162(l0, l1);
        }
    }
}

// ---------------- launch ------------------------------------------------
extern "C" void kernel_launch(void* const* d_in, const int* in_sizes, int n_in,
                              void* d_out, int out_size)
{
    const float* q1  = (const float*)d_in[0];
    const float* q2  = (const float*)d_in[1];
    const float* key = (const float*)d_in[2];
    const float* val = (const float*)d_in[3];
    const float* Wq  = (const float*)d_in[4];
    const float* bq  = (const float*)d_in[5];
    const float* Wq2 = (const float*)d_in[6];
    const float* bq2 = (const float*)d_in[7];
    const float* Wq3 = (const float*)d_in[8];
    const float* bq3 = (const float*)d_in[9];
    const float* Wk  = (const float*)d_in[10];
    const float* bk  = (const float*)d_in[11];
    const float* Wv  = (const float*)d_in[12];
    const float* bv  = (const float*)d_in[13];
    const float* Wo  = (const float*)d_in[14];
    const float* bo  = (const float*)d_in[15];

    float* out = (float*)d_out;                      // [B,T,E]
    float* a1  = out + (size_t)BB * TT * EE;         // [B,H,T,T]

    bf16 *Xhi, *Xlo, *Whi, *Wlo, *Qhi, *Qlo, *AOhi, *AOlo;
    float* V;
    cudaGetSymbolAddress((void**)&Xhi, g_Xhi);
    cudaGetSymbolAddress((void**)&Xlo, g_Xlo);
    cudaGetSymbolAddress((void**)&Whi, g_Whi);
    cudaGetSymbolAddress((void**)&Wlo, g_Wlo);
    cudaGetSymbolAddress((void**)&Qhi, g_Qhi);
    cudaGetSymbolAddress((void**)&Qlo, g_Qlo);
    cudaGetSymbolAddress((void**)&AOhi, g_AOhi);
    cudaGetSymbolAddress((void**)&AOlo, g_AOlo);
    cudaGetSymbolAddress((void**)&V, g_V);

    cudaFuncSetAttribute(k_gemm_x3, cudaFuncAttributeMaxDynamicSharedMemorySize, GEMM_SMEM);
    cudaFuncSetAttribute(k_score,   cudaFuncAttributeMaxDynamicSharedMemorySize, SC_SMEM);

    k_zero_sums<<<1, 128>>>();

    // splits
    SplitArgs si = {};
    const float* xs[4] = { q1, q2, key, val };
    for (int i = 0; i < 4; i++) {
        si.src[i] = xs[i];
        si.hi[i] = Xhi + (size_t)i * NTOK * EE;
        si.lo[i] = Xlo + (size_t)i * NTOK * EE;
    }
    k_split<<<dim3((NTOK * EE / 4) / 256, 4), 256>>>(si, NTOK * EE / 4);

    SplitArgs sw = {};
    const float* ws[6] = { Wq, Wq2, Wq3, Wk, Wv, Wo };
    for (int i = 0; i < 6; i++) {
        sw.src[i] = ws[i];
        sw.hi[i] = Whi + (size_t)i * EE * EE;
        sw.lo[i] = Wlo + (size_t)i * EE * EE;
    }
    k_split<<<dim3((EE * EE / 4) / 256, 6), 256>>>(sw, EE * EE / 4);

    // projections: Q1,Q2,Q3,K (split out) + V (fp32 out) in one launch
    GArgs pa = {};
    const int aidx[5] = { 0, 1, 2, 2, 3 };           // q1, q2, key, key, value
    const float* bs[5] = { bq, bq2, bq3, bk, bv };
    for (int p = 0; p < 5; p++) {
        pa.g[p].Ahi = Xhi + (size_t)aidx[p] * NTOK * EE;
        pa.g[p].Alo = Xlo + (size_t)aidx[p] * NTOK * EE;
        pa.g[p].Whi = Whi + (size_t)p * EE * EE;
        pa.g[p].Wlo = Wlo + (size_t)p * EE * EE;
        pa.g[p].bias = bs[p];
        if (p < 4) {
            pa.g[p].Chi = Qhi + (size_t)p * NTOK * EE;
            pa.g[p].Clo = Qlo + (size_t)p * NTOK * EE;
            pa.g[p].Cf = nullptr;
        } else {
            pa.g[p].Chi = nullptr; pa.g[p].Clo = nullptr;
            pa.g[p].Cf = V;
        }
    }
    k_gemm_x3<<<dim3(EE / 128, NTOK / 128, 5), 256, GEMM_SMEM>>>(pa);

    k_score<<<dim3(TT / 128, TT / 128, 3 * NBH), 256, SC_SMEM>>>(a1);

    k_av<<<dim3(TT / 128, NBH), 256>>>(a1);

    GArgs fo = {};
    fo.g[0].Ahi = AOhi; fo.g[0].Alo = AOlo;
    fo.g[0].Whi = Whi + (size_t)5 * EE * EE;
    fo.g[0].Wlo = Wlo + (size_t)5 * EE * EE;
    fo.g[0].bias = bo;
    fo.g[0].Chi = nullptr; fo.g[0].Clo = nullptr;
    fo.g[0].Cf = out;
    k_gemm_x3<<<dim3(EE / 128, NTOK / 128, 1), 256, GEMM_SMEM>>>(fo);
}

// round 6
// speedup vs baseline: 2.8477x; 1.0316x over previous
#include <cuda_runtime.h>
#include <cuda_bf16.h>
#include <cuda_fp16.h>
#include <cstdint>

#define BB 2
#define TT 1024
#define EE 1024
#define HH 16
#define HD 64
#define NTOK (BB*TT)      // 2048
#define NBH  (BB*HH)      // 32
#define ALPHA 0.25f       // (1/sqrt(HD)) / TEMP
#define ESC 0.03125f      // exp storage scale (1/32)
#define ESCI 32.0f

typedef __nv_bfloat16  bf16;
typedef __nv_bfloat162 bf162;

// ---------------- device scratch (no allocation allowed) ----------------
__device__ bf16  g_Xhi[4][(size_t)NTOK * EE], g_Xlo[4][(size_t)NTOK * EE]; // q1,q2,key,value splits
__device__ bf16  g_Whi[6][(size_t)EE * EE],   g_Wlo[6][(size_t)EE * EE];   // weight splits
__device__ bf16  g_Qhi[4][(size_t)NTOK * EE], g_Qlo[4][(size_t)NTOK * EE]; // Q1,Q2,Q3,K projections (split)
__device__ float g_V[(size_t)NTOK * EE];                                   // V projection fp32
__device__ __half g_Eh[3][(size_t)NBH * TT * TT];                          // exp scores, fp16, x(1/32)
__device__ bf16  g_AOhi[(size_t)NTOK * EE], g_AOlo[(size_t)NTOK * EE];     // attn out (split)
__device__ double g_sums[3 * NBH];                                         // softmax denominators

// ---------------- low-level helpers -------------------------------------
__device__ __forceinline__ uint32_t s2u(const void* p) {
    return (uint32_t)__cvta_generic_to_shared(p);
}
__device__ __forceinline__ void cpasync16(uint32_t s, const void* g) {
    asm volatile("cp.async.cg.shared.global [%0], [%1], 16;\n" :: "r"(s), "l"(g));
}
#define CP_COMMIT asm volatile("cp.async.commit_group;\n")
#define CP_WAIT1  asm volatile("cp.async.wait_group 1;\n")
#define CP_WAIT0  asm volatile("cp.async.wait_group 0;\n")

__device__ __forceinline__ void ldsm4(uint32_t a, uint32_t& r0, uint32_t& r1, uint32_t& r2, uint32_t& r3) {
    asm volatile("ldmatrix.sync.aligned.m8n8.x4.shared.b16 {%0,%1,%2,%3}, [%4];\n"
                 : "=r"(r0), "=r"(r1), "=r"(r2), "=r"(r3) : "r"(a));
}
__device__ __forceinline__ void ldsm4t(uint32_t a, uint32_t& r0, uint32_t& r1, uint32_t& r2, uint32_t& r3) {
    asm volatile("ldmatrix.sync.aligned.m8n8.x4.trans.shared.b16 {%0,%1,%2,%3}, [%4];\n"
                 : "=r"(r0), "=r"(r1), "=r"(r2), "=r"(r3) : "r"(a));
}
__device__ __forceinline__ void mma16816(float4& d, const uint32_t* a, const uint32_t* b) {
    asm volatile(
        "mma.sync.aligned.m16n8k16.row.col.f32.bf16.bf16.f32 "
        "{%0,%1,%2,%3}, {%4,%5,%6,%7}, {%8,%9}, {%0,%1,%2,%3};\n"
        : "+f"(d.x), "+f"(d.y), "+f"(d.z), "+f"(d.w)
        : "r"(a[0]), "r"(a[1]), "r"(a[2]), "r"(a[3]),
          "r"(b[0]), "r"(b[1]));
}
__device__ __forceinline__ void split1(float v, bf16& h, bf16& l) {
    h = __float2bfloat16_rn(v);
    l = __float2bfloat16_rn(v - __bfloat162float(h));
}

// ---------------- shared mma block: one k16 step -------------------------
template<int SKH>
__device__ __forceinline__ void mma_block16(
    const bf16* sAh, const bf16* sAl, const bf16* sBh, const bf16* sBl,
    int ko, int wm, int wn, int lane, float4 acc[4][4])
{
    uint32_t ah[4][4], al[4][4], bh[4][2], bl[4][2];
    const int arow = wm * 64 + (lane & 15);
    const int ak = ko + (lane >> 4) * 8;
#pragma unroll
    for (int mt = 0; mt < 4; mt++) {
        ldsm4(s2u(sAh + (arow + mt * 16) * SKH + ak), ah[mt][0], ah[mt][1], ah[mt][2], ah[mt][3]);
        ldsm4(s2u(sAl + (arow + mt * 16) * SKH + ak), al[mt][0], al[mt][1], al[mt][2], al[mt][3]);
    }
    const int brow = wn * 32 + ((lane >> 4) & 1) * 8 + (lane & 7);
    const int bk = ko + ((lane >> 3) & 1) * 8;
#pragma unroll
    for (int p2 = 0; p2 < 2; p2++) {
        uint32_t r0, r1, r2, r3;
        ldsm4(s2u(sBh + (brow + p2 * 16) * SKH + bk), r0, r1, r2, r3);
        bh[p2 * 2][0] = r0; bh[p2 * 2][1] = r1; bh[p2 * 2 + 1][0] = r2; bh[p2 * 2 + 1][1] = r3;
        ldsm4(s2u(sBl + (brow + p2 * 16) * SKH + bk), r0, r1, r2, r3);
        bl[p2 * 2][0] = r0; bl[p2 * 2][1] = r1; bl[p2 * 2 + 1][0] = r2; bl[p2 * 2 + 1][1] = r3;
    }
#pragma unroll
    for (int mt = 0; mt < 4; mt++)
#pragma unroll
        for (int nt = 0; nt < 4; nt++) {
            mma16816(acc[mt][nt], ah[mt], bh[nt]);
            mma16816(acc[mt][nt], ah[mt], bl[nt]);
            mma16816(acc[mt][nt], al[mt], bh[nt]);
        }
}

// ---------------- zero softmax sums -------------------------------------
__global__ void k_zero_sums() {
    int i = threadIdx.x;
    if (i < 3 * NBH) g_sums[i] = 0.0;
}

// ---------------- fp32 -> bf16 hi/lo split ------------------------------
struct SplitArgs { const float* src[6]; bf16* hi[6]; bf16* lo[6]; };

__global__ __launch_bounds__(256) void k_split(SplitArgs a, int n4) {
    const int z = blockIdx.y;
    const int i = blockIdx.x * 256 + threadIdx.x;
    if (i >= n4) return;
    float4 v = ((const float4*)a.src[z])[i];
    bf16 h0, l0, h1, l1, h2, l2, h3, l3;
    split1(v.x, h0, l0); split1(v.y, h1, l1);
    split1(v.z, h2, l2); split1(v.w, h3, l3);
    bf162* hp = (bf162*)a.hi[z];
    bf162* lp = (bf162*)a.lo[z];
    hp[i * 2]     = __halves2bfloat162(h0, h1);
    hp[i * 2 + 1] = __halves2bfloat162(h2, h3);
    lp[i * 2]     = __halves2bfloat162(l0, l1);
    lp[i * 2 + 1] = __halves2bfloat162(l2, l3);
}

// ---------------- bf16x3 GEMM + bias, cp.async 2-stage, ldmatrix --------
// C[M,N] = A[M,K] * W[N,K]^T + bias, K = EE. grid (N/128, M/128, batch).
struct GArg {
    const bf16 *Ahi, *Alo, *Whi, *Wlo;
    const float* bias;
    bf16 *Chi, *Clo;   // split-output mode if Cf == nullptr
    float* Cf;         // fp32-output mode
};
struct GArgs { GArg g[5]; };

#define GEMM_SKH 40
#define GEMM_SPL (128 * GEMM_SKH)
#define GEMM_STG (4 * GEMM_SPL)
#define GEMM_SMEM (2 * GEMM_STG * 2)   // bytes

__global__ __launch_bounds__(256) void k_gemm_x3(GArgs args) {
    extern __shared__ __align__(16) bf16 sm[];
    const GArg ga = args.g[blockIdx.z];

    const int tid = threadIdx.x;
    const int lane = tid & 31, warp = tid >> 5;
    const int wm = warp >> 2, wn = warp & 3;
    const int m0 = blockIdx.y * 128, n0 = blockIdx.x * 128;

    const int r = tid & 127, c0 = tid >> 7;
    const bf16* gp[4] = {
        ga.Ahi + (size_t)(m0 + r) * EE,
        ga.Alo + (size_t)(m0 + r) * EE,
        ga.Whi + (size_t)(n0 + r) * EE,
        ga.Wlo + (size_t)(n0 + r) * EE
    };
    const uint32_t sbase = s2u(sm);

    auto issue = [&](int kc, int p) {
#pragma unroll
        for (int mat = 0; mat < 4; mat++)
#pragma unroll
            for (int e = 0; e < 2; e++) {
                const int cc = c0 + 2 * e;
                uint32_t sa = sbase + (uint32_t)(p * GEMM_STG + mat * GEMM_SPL + r * GEMM_SKH + cc * 8) * 2;
                cpasync16(sa, gp[mat] + kc * 32 + cc * 8);
            }
    };
    issue(0, 0); CP_COMMIT;
    issue(1, 1); CP_COMMIT;

    float4 acc[4][4];
#pragma unroll
    for (int i = 0; i < 4; i++)
#pragma unroll
        for (int j = 0; j < 4; j++) acc[i][j] = make_float4(0.f, 0.f, 0.f, 0.f);

    for (int kc = 0; kc < EE / 32; kc++) {
        CP_WAIT1;
        __syncthreads();
        const int p = kc & 1;
        const bf16* sAh = sm + p * GEMM_STG;
        const bf16* sAl = sAh + GEMM_SPL;
        const bf16* sBh = sAl + GEMM_SPL;
        const bf16* sBl = sBh + GEMM_SPL;
        mma_block16<GEMM_SKH>(sAh, sAl, sBh, sBl, 0,  wm, wn, lane, acc);
        mma_block16<GEMM_SKH>(sAh, sAl, sBh, sBl, 16, wm, wn, lane, acc);
        __syncthreads();
        if (kc + 2 < EE / 32) issue(kc + 2, p);
        CP_COMMIT;
    }

    const int r4 = lane >> 2, q2 = (lane & 3) * 2;
#pragma unroll
    for (int mt = 0; mt < 4; mt++) {
        const int row = m0 + wm * 64 + mt * 16 + r4;
#pragma unroll
        for (int nt = 0; nt < 4; nt++) {
            const int col = n0 + wn * 32 + nt * 8 + q2;
            const float bx = ga.bias[col], by = ga.bias[col + 1];
            const float vx = acc[mt][nt].x + bx, vy = acc[mt][nt].y + by;
            const float vz = acc[mt][nt].z + bx, vw = acc[mt][nt].w + by;
            if (ga.Cf) {
                *(float2*)&ga.Cf[(size_t)row * EE + col]       = make_float2(vx, vy);
                *(float2*)&ga.Cf[(size_t)(row + 8) * EE + col] = make_float2(vz, vw);
            } else {
                bf16 h0, l0, h1, l1;
                split1(vx, h0, l0); split1(vy, h1, l1);
                *(bf162*)&ga.Chi[(size_t)row * EE + col] = __halves2bfloat162(h0, h1);
                *(bf162*)&ga.Clo[(size_t)row * EE + col] = __halves2bfloat162(l0, l1);
                split1(vz, h0, l0); split1(vw, h1, l1);
                *(bf162*)&ga.Chi[(size_t)(row + 8) * EE + col] = __halves2bfloat162(h0, h1);
                *(bf162*)&ga.Clo[(size_t)(row + 8) * EE + col] = __halves2bfloat162(l0, l1);
            }
        }
    }
}

// ---------------- scores: exp((Qh Kh^T)*ALPHA)*ESC -> fp16, fused sum ----
// K=64 staged whole via cp.async. grid (8, 8, 96): z = tensor*32 + bh
#define SC_SKH 72
#define SC_SPL (128 * SC_SKH)
#define SC_SMEM (4 * SC_SPL * 2 + 1024)

__global__ __launch_bounds__(256) void k_score() {
    extern __shared__ __align__(16) bf16 sm[];
    float* red = (float*)(sm + 4 * SC_SPL);

    const int zz = blockIdx.z;
    const int tensor = zz >> 5, bh = zz & 31;
    const int b = bh >> 4, h = bh & 15;
    const size_t hofs = (size_t)b * TT * EE + h * HD;

    const bf16* Qh = g_Qhi[tensor] + hofs;
    const bf16* Ql = g_Qlo[tensor] + hofs;
    const bf16* Kh = g_Qhi[3] + hofs;
    const bf16* Kl = g_Qlo[3] + hofs;
    __half* Eo = g_Eh[tensor] + (size_t)bh * TT * TT;

    const int tid = threadIdx.x;
    const int lane = tid & 31, warp = tid >> 5;
    const int wm = warp >> 2, wn = warp & 3;
    const int m0 = blockIdx.y * 128, n0 = blockIdx.x * 128;

    const int r = tid & 127, c0 = tid >> 7;
    const bf16* gp[4] = {
        Qh + (size_t)(m0 + r) * EE, Ql + (size_t)(m0 + r) * EE,
        Kh + (size_t)(n0 + r) * EE, Kl + (size_t)(n0 + r) * EE
    };
    const uint32_t sbase = s2u(sm);
#pragma unroll
    for (int mat = 0; mat < 4; mat++)
#pragma unroll
        for (int e = 0; e < 4; e++) {
            const int cc = c0 + 2 * e;
            cpasync16(sbase + (uint32_t)(mat * SC_SPL + r * SC_SKH + cc * 8) * 2, gp[mat] + cc * 8);
        }
    CP_COMMIT; CP_WAIT0;
    __syncthreads();

    float4 acc[4][4];
#pragma unroll
    for (int i = 0; i < 4; i++)
#pragma unroll
        for (int j = 0; j < 4; j++) acc[i][j] = make_float4(0.f, 0.f, 0.f, 0.f);

    const bf16* sAh = sm;
    const bf16* sAl = sAh + SC_SPL;
    const bf16* sBh = sAl + SC_SPL;
    const bf16* sBl = sBh + SC_SPL;
#pragma unroll
    for (int ko = 0; ko < 64; ko += 16)
        mma_block16<SC_SKH>(sAh, sAl, sBh, sBl, ko, wm, wn, lane, acc);

    const int r4 = lane >> 2, q2 = (lane & 3) * 2;
    float lsum = 0.f;
#pragma unroll
    for (int mt = 0; mt < 4; mt++) {
        const int row = m0 + wm * 64 + mt * 16 + r4;
#pragma unroll
        for (int nt = 0; nt < 4; nt++) {
            const int col = n0 + wn * 32 + nt * 8 + q2;
            const float vx = __expf(acc[mt][nt].x * ALPHA);
            const float vy = __expf(acc[mt][nt].y * ALPHA);
            const float vz = __expf(acc[mt][nt].z * ALPHA);
            const float vw = __expf(acc[mt][nt].w * ALPHA);
            *(__half2*)&Eo[(size_t)row * TT + col]       = __floats2half2_rn(vx * ESC, vy * ESC);
            *(__half2*)&Eo[(size_t)(row + 8) * TT + col] = __floats2half2_rn(vz * ESC, vw * ESC);
            lsum += vx + vy + vz + vw;
        }
    }
    red[tid] = lsum;
    __syncthreads();
    for (int s = 128; s > 0; s >>= 1) {
        if (tid < s) red[tid] += red[tid + s];
        __syncthreads();
    }
    if (tid == 0) atomicAdd(&g_sums[zz], (double)red[0]);
}

// ---------------- AV: ((a1+a2+a3)/3) @ V, fp16 E streams, a1 writeback --
// grid (TT/128, NBH). Writes fp32 a1 = c1*E1 and bf16x3 AO.
__global__ __launch_bounds__(256) void k_av(float* __restrict__ a1out) {
    __shared__ bf16 sW[2][128 * 40];   // W hi/lo, [t][s] stride 40
    __shared__ bf16 sV[2][32 * 72];    // V hi/lo, [s][d] stride 72

    const int bh = blockIdx.y;
    const int b = bh >> 4, h = bh & 15;
    const int t0 = blockIdx.x * 128;

    const float c1 = (float)((double)TT / g_sums[bh]) * ESCI;
    const float c2 = (float)((double)TT / g_sums[32 + bh]) * ESCI;
    const float c3 = (float)((double)TT / g_sums[64 + bh]) * ESCI;
    const float third = 1.0f / 3.0f;

    const __half* E1p = g_Eh[0] + (size_t)bh * TT * TT;
    const __half* E2p = g_Eh[1] + (size_t)bh * TT * TT;
    const __half* E3p = g_Eh[2] + (size_t)bh * TT * TT;
    float* a1p = a1out + (size_t)bh * TT * TT;
    const float* Vp  = g_V + (size_t)b * TT * EE + h * HD;

    const int tid = threadIdx.x;
    const int lane = tid & 31, warp = tid >> 5;
    const int wm = warp >> 2, wn = warp & 3;

    float4 acc[4][2];
#pragma unroll
    for (int i = 0; i < 4; i++)
#pragma unroll
        for (int j = 0; j < 2; j++) acc[i][j] = make_float4(0.f, 0.f, 0.f, 0.f);

    for (int s0 = 0; s0 < TT; s0 += 32) {
#pragma unroll
        for (int e = 0; e < 4; e++) {
            const int lin = tid + e * 256;          // 0..1023
            const int t = lin >> 3, s4 = (lin & 7) * 4;
            const size_t ei = (size_t)(t0 + t) * TT + s0 + s4;
            const uint2 u1 = *(const uint2*)&E1p[ei];
            const uint2 u2 = *(const uint2*)&E2p[ei];
            const uint2 u3 = *(const uint2*)&E3p[ei];
            const float2 e1a = __half22float2(*(const __half2*)&u1.x);
            const float2 e1b = __half22float2(*(const __half2*)&u1.y);
            const float2 e2a = __half22float2(*(const __half2*)&u2.x);
            const float2 e2b = __half22float2(*(const __half2*)&u2.y);
            const float2 e3a = __half22float2(*(const __half2*)&u3.x);
            const float2 e3b = __half22float2(*(const __half2*)&u3.y);
            const float4 a1v = make_float4(e1a.x * c1, e1a.y * c1, e1b.x * c1, e1b.y * c1);
            *(float4*)&a1p[ei] = a1v;               // scaled a1 -> d_out
            const float w0 = (a1v.x + e2a.x * c2 + e3a.x * c3) * third;
            const float w1 = (a1v.y + e2a.y * c2 + e3a.y * c3) * third;
            const float w2 = (a1v.z + e2b.x * c2 + e3b.x * c3) * third;
            const float w3 = (a1v.w + e2b.y * c2 + e3b.y * c3) * third;
            bf16 h0, l0, h1, l1, h2, l2, h3, l3;
            split1(w0, h0, l0); split1(w1, h1, l1);
            split1(w2, h2, l2); split1(w3, h3, l3);
            *(bf162*)&sW[0][t * 40 + s4]     = __halves2bfloat162(h0, h1);
            *(bf162*)&sW[0][t * 40 + s4 + 2] = __halves2bfloat162(h2, h3);
            *(bf162*)&sW[1][t * 40 + s4]     = __halves2bfloat162(l0, l1);
            *(bf162*)&sW[1][t * 40 + s4 + 2] = __halves2bfloat162(l2, l3);
        }
#pragma unroll
        for (int e = 0; e < 2; e++) {
            const int lin = tid + e * 256;          // 0..511
            const int s = lin >> 4, d4 = (lin & 15) * 4;
            float4 v = *(const float4*)&Vp[(size_t)(s0 + s) * EE + d4];
            bf16 h0, l0, h1, l1, h2, l2, h3, l3;
            split1(v.x, h0, l0); split1(v.y, h1, l1);
            split1(v.z, h2, l2); split1(v.w, h3, l3);
            *(bf162*)&sV[0][s * 72 + d4]     = __halves2bfloat162(h0, h1);
            *(bf162*)&sV[0][s * 72 + d4 + 2] = __halves2bfloat162(h2, h3);
            *(bf162*)&sV[1][s * 72 + d4]     = __halves2bfloat162(l0, l1);
            *(bf162*)&sV[1][s * 72 + d4 + 2] = __halves2bfloat162(l2, l3);
        }
        __syncthreads();
#pragma unroll
        for (int ks = 0; ks < 32; ks += 16) {
            uint32_t ah[4][4], al[4][4], bv[2][2][2];
            const int arow = wm * 64 + (lane & 15);
            const int ak = ks + (lane >> 4) * 8;
#pragma unroll
            for (int mt = 0; mt < 4; mt++) {
                ldsm4(s2u(&sW[0][(arow + mt * 16) * 40 + ak]), ah[mt][0], ah[mt][1], ah[mt][2], ah[mt][3]);
                ldsm4(s2u(&sW[1][(arow + mt * 16) * 40 + ak]), al[mt][0], al[mt][1], al[mt][2], al[mt][3]);
            }
            const int srow = ks + ((lane >> 3) & 1) * 8 + (lane & 7);
            const int dcol = wn * 16 + ((lane >> 4) & 1) * 8;
#pragma unroll
            for (int sg = 0; sg < 2; sg++) {
                uint32_t r0, r1, r2, r3;
                ldsm4t(s2u(&sV[sg][srow * 72 + dcol]), r0, r1, r2, r3);
                bv[sg][0][0] = r0; bv[sg][0][1] = r1;
                bv[sg][1][0] = r2; bv[sg][1][1] = r3;
            }
#pragma unroll
            for (int mt = 0; mt < 4; mt++)
#pragma unroll
                for (int nt = 0; nt < 2; nt++) {
                    mma16816(acc[mt][nt], ah[mt], bv[0][nt]);
                    mma16816(acc[mt][nt], ah[mt], bv[1][nt]);
                    mma16816(acc[mt][nt], al[mt], bv[0][nt]);
                }
        }
        __syncthreads();
    }

    const int r4 = lane >> 2, q2 = (lane & 3) * 2;
#pragma unroll
    for (int mt = 0; mt < 4; mt++) {
        const int trow = t0 + wm * 64 + mt * 16 + r4;
#pragma unroll
        for (int nt = 0; nt < 2; nt++) {
            const int col = h * HD + wn * 16 + nt * 8 + q2;
            bf16 h0, l0, h1, l1;
            const size_t base0 = (size_t)(b * TT + trow) * EE + col;
            split1(acc[mt][nt].x, h0, l0); split1(acc[mt][nt].y, h1, l1);
            *(bf162*)&g_AOhi[base0] = __halves2bfloat162(h0, h1);
            *(bf162*)&g_AOlo[base0] = __halves2bfloat162(l0, l1);
            const size_t base1 = (size_t)(b * TT + trow + 8) * EE + col;
            split1(acc[mt][nt].z, h0, l0); split1(acc[mt][nt].w, h1, l1);
            *(bf162*)&g_AOhi[base1] = __halves2bfloat162(h0, h1);
            *(bf162*)&g_AOlo[base1] = __halves2bfloat162(l0, l1);
        }
    }
}

// ---------------- launch ------------------------------------------------
extern "C" void kernel_launch(void* const* d_in, const int* in_sizes, int n_in,
                              void* d_out, int out_size)
{
    const float* q1  = (const float*)d_in[0];
    const float* q2  = (const float*)d_in[1];
    const float* key = (const float*)d_in[2];
    const float* val = (const float*)d_in[3];
    const float* Wq  = (const float*)d_in[4];
    const float* bq  = (const float*)d_in[5];
    const float* Wq2 = (const float*)d_in[6];
    const float* bq2 = (const float*)d_in[7];
    const float* Wq3 = (const float*)d_in[8];
    const float* bq3 = (const float*)d_in[9];
    const float* Wk  = (const float*)d_in[10];
    const float* bk  = (const float*)d_in[11];
    const float* Wv  = (const float*)d_in[12];
    const float* bv  = (const float*)d_in[13];
    const float* Wo  = (const float*)d_in[14];
    const float* bo  = (const float*)d_in[15];

    float* out = (float*)d_out;                      // [B,T,E]
    float* a1  = out + (size_t)BB * TT * EE;         // [B,H,T,T]

    bf16 *Xhi, *Xlo, *Whi, *Wlo, *Qhi, *Qlo, *AOhi, *AOlo;
    float* V;
    cudaGetSymbolAddress((void**)&Xhi, g_Xhi);
    cudaGetSymbolAddress((void**)&Xlo, g_Xlo);
    cudaGetSymbolAddress((void**)&Whi, g_Whi);
    cudaGetSymbolAddress((void**)&Wlo, g_Wlo);
    cudaGetSymbolAddress((void**)&Qhi, g_Qhi);
    cudaGetSymbolAddress((void**)&Qlo, g_Qlo);
    cudaGetSymbolAddress((void**)&AOhi, g_AOhi);
    cudaGetSymbolAddress((void**)&AOlo, g_AOlo);
    cudaGetSymbolAddress((void**)&V, g_V);

    cudaFuncSetAttribute(k_gemm_x3, cudaFuncAttributeMaxDynamicSharedMemorySize, GEMM_SMEM);
    cudaFuncSetAttribute(k_score,   cudaFuncAttributeMaxDynamicSharedMemorySize, SC_SMEM);

    k_zero_sums<<<1, 128>>>();

    // splits
    SplitArgs si = {};
    const float* xs[4] = { q1, q2, key, val };
    for (int i = 0; i < 4; i++) {
        si.src[i] = xs[i];
        si.hi[i] = Xhi + (size_t)i * NTOK * EE;
        si.lo[i] = Xlo + (size_t)i * NTOK * EE;
    }
    k_split<<<dim3((NTOK * EE / 4) / 256, 4), 256>>>(si, NTOK * EE / 4);

    SplitArgs sw = {};
    const float* ws[6] = { Wq, Wq2, Wq3, Wk, Wv, Wo };
    for (int i = 0; i < 6; i++) {
        sw.src[i] = ws[i];
        sw.hi[i] = Whi + (size_t)i * EE * EE;
        sw.lo[i] = Wlo + (size_t)i * EE * EE;
    }
    k_split<<<dim3((EE * EE / 4) / 256, 6), 256>>>(sw, EE * EE / 4);

    // projections: Q1,Q2,Q3,K (split out) + V (fp32 out) in one launch
    GArgs pa = {};
    const int aidx[5] = { 0, 1, 2, 2, 3 };           // q1, q2, key, key, value
    const float* bs[5] = { bq, bq2, bq3, bk, bv };
    for (int p = 0; p < 5; p++) {
        pa.g[p].Ahi = Xhi + (size_t)aidx[p] * NTOK * EE;
        pa.g[p].Alo = Xlo + (size_t)aidx[p] * NTOK * EE;
        pa.g[p].Whi = Whi + (size_t)p * EE * EE;
        pa.g[p].Wlo = Wlo + (size_t)p * EE * EE;
        pa.g[p].bias = bs[p];
        if (p < 4) {
            pa.g[p].Chi = Qhi + (size_t)p * NTOK * EE;
            pa.g[p].Clo = Qlo + (size_t)p * NTOK * EE;
            pa.g[p].Cf = nullptr;
        } else {
            pa.g[p].Chi = nullptr; pa.g[p].Clo = nullptr;
            pa.g[p].Cf = V;
        }
    }
    k_gemm_x3<<<dim3(EE / 128, NTOK / 128, 5), 256, GEMM_SMEM>>>(pa);

    k_score<<<dim3(TT / 128, TT / 128, 3 * NBH), 256, SC_SMEM>>>();

    k_av<<<dim3(TT / 128, NBH), 256>>>(a1);

    GArgs fo = {};
    fo.g[0].Ahi = AOhi; fo.g[0].Alo = AOlo;
    fo.g[0].Whi = Whi + (size_t)5 * EE * EE;
    fo.g[0].Wlo = Wlo + (size_t)5 * EE * EE;
    fo.g[0].bias = bo;
    fo.g[0].Chi = nullptr; fo.g[0].Clo = nullptr;
    fo.g[0].Cf = out;
    k_gemm_x3<<<dim3(EE / 128, NTOK / 128, 1), 256, GEMM_SMEM>>>(fo);
}

// round 7
// speedup vs baseline: 2.8607x; 1.0046x over previous
#include <cuda_runtime.h>
#include <cuda_bf16.h>
#include <cuda_fp16.h>
#include <cstdint>

#define BB 2
#define TT 1024
#define EE 1024
#define HH 16
#define HD 64
#define NTOK (BB*TT)      // 2048
#define NBH  (BB*HH)      // 32
#define ALPHA 0.25f       // (1/sqrt(HD)) / TEMP
#define ESC 0.03125f      // exp storage scale (1/32)
#define ESCI 32.0f

typedef __nv_bfloat16  bf16;
typedef __nv_bfloat162 bf162;

// ---------------- device scratch (no allocation allowed) ----------------
__device__ bf16  g_Xhi[4][(size_t)NTOK * EE], g_Xlo[4][(size_t)NTOK * EE]; // q1,q2,key,value splits
__device__ bf16  g_Whi[6][(size_t)EE * EE],   g_Wlo[6][(size_t)EE * EE];   // weight splits
__device__ bf16  g_Qhi[4][(size_t)NTOK * EE], g_Qlo[4][(size_t)NTOK * EE]; // Q1,Q2,Q3,K projections (split)
__device__ float g_V[(size_t)NTOK * EE];                                   // V projection fp32
__device__ __half g_Eh[3][(size_t)NBH * TT * TT];                          // exp scores, fp16, x(1/32)
__device__ bf16  g_AOhi[(size_t)NTOK * EE], g_AOlo[(size_t)NTOK * EE];     // attn out (split)
__device__ double g_sums[3 * NBH];                                         // softmax denominators

// ---------------- low-level helpers -------------------------------------
__device__ __forceinline__ uint32_t s2u(const void* p) {
    return (uint32_t)__cvta_generic_to_shared(p);
}
__device__ __forceinline__ void cpasync16(uint32_t s, const void* g) {
    asm volatile("cp.async.cg.shared.global [%0], [%1], 16;\n" :: "r"(s), "l"(g));
}
#define CP_COMMIT asm volatile("cp.async.commit_group;\n")
#define CP_WAIT1  asm volatile("cp.async.wait_group 1;\n")
#define CP_WAIT0  asm volatile("cp.async.wait_group 0;\n")

__device__ __forceinline__ void ldsm4(uint32_t a, uint32_t& r0, uint32_t& r1, uint32_t& r2, uint32_t& r3) {
    asm volatile("ldmatrix.sync.aligned.m8n8.x4.shared.b16 {%0,%1,%2,%3}, [%4];\n"
                 : "=r"(r0), "=r"(r1), "=r"(r2), "=r"(r3) : "r"(a));
}
__device__ __forceinline__ void ldsm4t(uint32_t a, uint32_t& r0, uint32_t& r1, uint32_t& r2, uint32_t& r3) {
    asm volatile("ldmatrix.sync.aligned.m8n8.x4.trans.shared.b16 {%0,%1,%2,%3}, [%4];\n"
                 : "=r"(r0), "=r"(r1), "=r"(r2), "=r"(r3) : "r"(a));
}
__device__ __forceinline__ void mma16816(float4& d, const uint32_t* a, const uint32_t* b) {
    asm volatile(
        "mma.sync.aligned.m16n8k16.row.col.f32.bf16.bf16.f32 "
        "{%0,%1,%2,%3}, {%4,%5,%6,%7}, {%8,%9}, {%0,%1,%2,%3};\n"
        : "+f"(d.x), "+f"(d.y), "+f"(d.z), "+f"(d.w)
        : "r"(a[0]), "r"(a[1]), "r"(a[2]), "r"(a[3]),
          "r"(b[0]), "r"(b[1]));
}
__device__ __forceinline__ void split1(float v, bf16& h, bf16& l) {
    h = __float2bfloat16_rn(v);
    l = __float2bfloat16_rn(v - __bfloat162float(h));
}

// ---------------- shared mma block: one k16 step -------------------------
// REORDERED: three full product passes (hi*hi, hi*lo, lo*hi) so that
// same-accumulator HMMA dependency distance is 16 instructions, not 1.
template<int SKH>
__device__ __forceinline__ void mma_block16(
    const bf16* sAh, const bf16* sAl, const bf16* sBh, const bf16* sBl,
    int ko, int wm, int wn, int lane, float4 acc[4][4])
{
    uint32_t ah[4][4], al[4][4], bh[4][2], bl[4][2];
    const int arow = wm * 64 + (lane & 15);
    const int ak = ko + (lane >> 4) * 8;
#pragma unroll
    for (int mt = 0; mt < 4; mt++) {
        ldsm4(s2u(sAh + (arow + mt * 16) * SKH + ak), ah[mt][0], ah[mt][1], ah[mt][2], ah[mt][3]);
        ldsm4(s2u(sAl + (arow + mt * 16) * SKH + ak), al[mt][0], al[mt][1], al[mt][2], al[mt][3]);
    }
    const int brow = wn * 32 + ((lane >> 4) & 1) * 8 + (lane & 7);
    const int bk = ko + ((lane >> 3) & 1) * 8;
#pragma unroll
    for (int p2 = 0; p2 < 2; p2++) {
        uint32_t r0, r1, r2, r3;
        ldsm4(s2u(sBh + (brow + p2 * 16) * SKH + bk), r0, r1, r2, r3);
        bh[p2 * 2][0] = r0; bh[p2 * 2][1] = r1; bh[p2 * 2 + 1][0] = r2; bh[p2 * 2 + 1][1] = r3;
        ldsm4(s2u(sBl + (brow + p2 * 16) * SKH + bk), r0, r1, r2, r3);
        bl[p2 * 2][0] = r0; bl[p2 * 2][1] = r1; bl[p2 * 2 + 1][0] = r2; bl[p2 * 2 + 1][1] = r3;
    }
    // pass 1: hi * hi
#pragma unroll
    for (int mt = 0; mt < 4; mt++)
#pragma unroll
        for (int nt = 0; nt < 4; nt++)
            mma16816(acc[mt][nt], ah[mt], bh[nt]);
    // pass 2: hi * lo
#pragma unroll
    for (int mt = 0; mt < 4; mt++)
#pragma unroll
        for (int nt = 0; nt < 4; nt++)
            mma16816(acc[mt][nt], ah[mt], bl[nt]);
    // pass 3: lo * hi
#pragma unroll
    for (int mt = 0; mt < 4; mt++)
#pragma unroll
        for (int nt = 0; nt < 4; nt++)
            mma16816(acc[mt][nt], al[mt], bh[nt]);
}

// ---------------- zero softmax sums -------------------------------------
__global__ void k_zero_sums() {
    int i = threadIdx.x;
    if (i < 3 * NBH) g_sums[i] = 0.0;
}

// ---------------- fp32 -> bf16 hi/lo split ------------------------------
struct SplitArgs { const float* src[6]; bf16* hi[6]; bf16* lo[6]; };

__global__ __launch_bounds__(256) void k_split(SplitArgs a, int n4) {
    const int z = blockIdx.y;
    const int i = blockIdx.x * 256 + threadIdx.x;
    if (i >= n4) return;
    float4 v = ((const float4*)a.src[z])[i];
    bf16 h0, l0, h1, l1, h2, l2, h3, l3;
    split1(v.x, h0, l0); split1(v.y, h1, l1);
    split1(v.z, h2, l2); split1(v.w, h3, l3);
    bf162* hp = (bf162*)a.hi[z];
    bf162* lp = (bf162*)a.lo[z];
    hp[i * 2]     = __halves2bfloat162(h0, h1);
    hp[i * 2 + 1] = __halves2bfloat162(h2, h3);
    lp[i * 2]     = __halves2bfloat162(l0, l1);
    lp[i * 2 + 1] = __halves2bfloat162(l2, l3);
}

// ---------------- bf16x3 GEMM + bias, cp.async 2-stage, ldmatrix --------
// C[M,N] = A[M,K] * W[N,K]^T + bias, K = EE. grid (N/128, M/128, batch).
struct GArg {
    const bf16 *Ahi, *Alo, *Whi, *Wlo;
    const float* bias;
    bf16 *Chi, *Clo;   // split-output mode if Cf == nullptr
    float* Cf;         // fp32-output mode
};
struct GArgs { GArg g[5]; };

#define GEMM_SKH 40
#define GEMM_SPL (128 * GEMM_SKH)
#define GEMM_STG (4 * GEMM_SPL)
#define GEMM_SMEM (2 * GEMM_STG * 2)   // bytes

__global__ __launch_bounds__(256) void k_gemm_x3(GArgs args) {
    extern __shared__ __align__(16) bf16 sm[];
    const GArg ga = args.g[blockIdx.z];

    const int tid = threadIdx.x;
    const int lane = tid & 31, warp = tid >> 5;
    const int wm = warp >> 2, wn = warp & 3;
    const int m0 = blockIdx.y * 128, n0 = blockIdx.x * 128;

    const int r = tid & 127, c0 = tid >> 7;
    const bf16* gp[4] = {
        ga.Ahi + (size_t)(m0 + r) * EE,
        ga.Alo + (size_t)(m0 + r) * EE,
        ga.Whi + (size_t)(n0 + r) * EE,
        ga.Wlo + (size_t)(n0 + r) * EE
    };
    const uint32_t sbase = s2u(sm);

    auto issue = [&](int kc, int p) {
#pragma unroll
        for (int mat = 0; mat < 4; mat++)
#pragma unroll
            for (int e = 0; e < 2; e++) {
                const int cc = c0 + 2 * e;
                uint32_t sa = sbase + (uint32_t)(p * GEMM_STG + mat * GEMM_SPL + r * GEMM_SKH + cc * 8) * 2;
                cpasync16(sa, gp[mat] + kc * 32 + cc * 8);
            }
    };
    issue(0, 0); CP_COMMIT;
    issue(1, 1); CP_COMMIT;

    float4 acc[4][4];
#pragma unroll
    for (int i = 0; i < 4; i++)
#pragma unroll
        for (int j = 0; j < 4; j++) acc[i][j] = make_float4(0.f, 0.f, 0.f, 0.f);

    for (int kc = 0; kc < EE / 32; kc++) {
        CP_WAIT1;
        __syncthreads();
        const int p = kc & 1;
        const bf16* sAh = sm + p * GEMM_STG;
        const bf16* sAl = sAh + GEMM_SPL;
        const bf16* sBh = sAl + GEMM_SPL;
        const bf16* sBl = sBh + GEMM_SPL;
        mma_block16<GEMM_SKH>(sAh, sAl, sBh, sBl, 0,  wm, wn, lane, acc);
        mma_block16<GEMM_SKH>(sAh, sAl, sBh, sBl, 16, wm, wn, lane, acc);
        __syncthreads();
        if (kc + 2 < EE / 32) issue(kc + 2, p);
        CP_COMMIT;
    }

    const int r4 = lane >> 2, q2 = (lane & 3) * 2;
#pragma unroll
    for (int mt = 0; mt < 4; mt++) {
        const int row = m0 + wm * 64 + mt * 16 + r4;
#pragma unroll
        for (int nt = 0; nt < 4; nt++) {
            const int col = n0 + wn * 32 + nt * 8 + q2;
            const float bx = ga.bias[col], by = ga.bias[col + 1];
            const float vx = acc[mt][nt].x + bx, vy = acc[mt][nt].y + by;
            const float vz = acc[mt][nt].z + bx, vw = acc[mt][nt].w + by;
            if (ga.Cf) {
                *(float2*)&ga.Cf[(size_t)row * EE + col]       = make_float2(vx, vy);
                *(float2*)&ga.Cf[(size_t)(row + 8) * EE + col] = make_float2(vz, vw);
            } else {
                bf16 h0, l0, h1, l1;
                split1(vx, h0, l0); split1(vy, h1, l1);
                *(bf162*)&ga.Chi[(size_t)row * EE + col] = __halves2bfloat162(h0, h1);
                *(bf162*)&ga.Clo[(size_t)row * EE + col] = __halves2bfloat162(l0, l1);
                split1(vz, h0, l0); split1(vw, h1, l1);
                *(bf162*)&ga.Chi[(size_t)(row + 8) * EE + col] = __halves2bfloat162(h0, h1);
                *(bf162*)&ga.Clo[(size_t)(row + 8) * EE + col] = __halves2bfloat162(l0, l1);
            }
        }
    }
}

// ---------------- scores: exp((Qh Kh^T)*ALPHA)*ESC -> fp16, fused sum ----
// K=64 staged whole via cp.async. grid (8, 8, 96): z = tensor*32 + bh
#define SC_SKH 72
#define SC_SPL (128 * SC_SKH)
#define SC_SMEM (4 * SC_SPL * 2 + 1024)

__global__ __launch_bounds__(256) void k_score() {
    extern __shared__ __align__(16) bf16 sm[];
    float* red = (float*)(sm + 4 * SC_SPL);

    const int zz = blockIdx.z;
    const int tensor = zz >> 5, bh = zz & 31;
    const int b = bh >> 4, h = bh & 15;
    const size_t hofs = (size_t)b * TT * EE + h * HD;

    const bf16* Qh = g_Qhi[tensor] + hofs;
    const bf16* Ql = g_Qlo[tensor] + hofs;
    const bf16* Kh = g_Qhi[3] + hofs;
    const bf16* Kl = g_Qlo[3] + hofs;
    __half* Eo = g_Eh[tensor] + (size_t)bh * TT * TT;

    const int tid = threadIdx.x;
    const int lane = tid & 31, warp = tid >> 5;
    const int wm = warp >> 2, wn = warp & 3;
    const int m0 = blockIdx.y * 128, n0 = blockIdx.x * 128;

    const int r = tid & 127, c0 = tid >> 7;
    const bf16* gp[4] = {
        Qh + (size_t)(m0 + r) * EE, Ql + (size_t)(m0 + r) * EE,
        Kh + (size_t)(n0 + r) * EE, Kl + (size_t)(n0 + r) * EE
    };
    const uint32_t sbase = s2u(sm);
#pragma unroll
    for (int mat = 0; mat < 4; mat++)
#pragma unroll
        for (int e = 0; e < 4; e++) {
            const int cc = c0 + 2 * e;
            cpasync16(sbase + (uint32_t)(mat * SC_SPL + r * SC_SKH + cc * 8) * 2, gp[mat] + cc * 8);
        }
    CP_COMMIT; CP_WAIT0;
    __syncthreads();

    float4 acc[4][4];
#pragma unroll
    for (int i = 0; i < 4; i++)
#pragma unroll
        for (int j = 0; j < 4; j++) acc[i][j] = make_float4(0.f, 0.f, 0.f, 0.f);

    const bf16* sAh = sm;
    const bf16* sAl = sAh + SC_SPL;
    const bf16* sBh = sAl + SC_SPL;
    const bf16* sBl = sBh + SC_SPL;
#pragma unroll
    for (int ko = 0; ko < 64; ko += 16)
        mma_block16<SC_SKH>(sAh, sAl, sBh, sBl, ko, wm, wn, lane, acc);

    const int r4 = lane >> 2, q2 = (lane & 3) * 2;
    float lsum = 0.f;
#pragma unroll
    for (int mt = 0; mt < 4; mt++) {
        const int row = m0 + wm * 64 + mt * 16 + r4;
#pragma unroll
        for (int nt = 0; nt < 4; nt++) {
            const int col = n0 + wn * 32 + nt * 8 + q2;
            const float vx = __expf(acc[mt][nt].x * ALPHA);
            const float vy = __expf(acc[mt][nt].y * ALPHA);
            const float vz = __expf(acc[mt][nt].z * ALPHA);
            const float vw = __expf(acc[mt][nt].w * ALPHA);
            *(__half2*)&Eo[(size_t)row * TT + col]       = __floats2half2_rn(vx * ESC, vy * ESC);
            *(__half2*)&Eo[(size_t)(row + 8) * TT + col] = __floats2half2_rn(vz * ESC, vw * ESC);
            lsum += vx + vy + vz + vw;
        }
    }
    red[tid] = lsum;
    __syncthreads();
    for (int s = 128; s > 0; s >>= 1) {
        if (tid < s) red[tid] += red[tid + s];
        __syncthreads();
    }
    if (tid == 0) atomicAdd(&g_sums[zz], (double)red[0]);
}

// ---------------- AV: ((a1+a2+a3)/3) @ V, fp16 E streams, a1 writeback --
// grid (TT/128, NBH). Writes fp32 a1 = c1*E1 and bf16x3 AO.
__global__ __launch_bounds__(256) void k_av(float* __restrict__ a1out) {
    __shared__ bf16 sW[2][128 * 40];   // W hi/lo, [t][s] stride 40
    __shared__ bf16 sV[2][32 * 72];    // V hi/lo, [s][d] stride 72

    const int bh = blockIdx.y;
    const int b = bh >> 4, h = bh & 15;
    const int t0 = blockIdx.x * 128;

    const float c1 = (float)((double)TT / g_sums[bh]) * ESCI;
    const float c2 = (float)((double)TT / g_sums[32 + bh]) * ESCI;
    const float c3 = (float)((double)TT / g_sums[64 + bh]) * ESCI;
    const float third = 1.0f / 3.0f;

    const __half* E1p = g_Eh[0] + (size_t)bh * TT * TT;
    const __half* E2p = g_Eh[1] + (size_t)bh * TT * TT;
    const __half* E3p = g_Eh[2] + (size_t)bh * TT * TT;
    float* a1p = a1out + (size_t)bh * TT * TT;
    const float* Vp  = g_V + (size_t)b * TT * EE + h * HD;

    const int tid = threadIdx.x;
    const int lane = tid & 31, warp = tid >> 5;
    const int wm = warp >> 2, wn = warp & 3;

    float4 acc[4][2];
#pragma unroll
    for (int i = 0; i < 4; i++)
#pragma unroll
        for (int j = 0; j < 2; j++) acc[i][j] = make_float4(0.f, 0.f, 0.f, 0.f);

    for (int s0 = 0; s0 < TT; s0 += 32) {
#pragma unroll
        for (int e = 0; e < 4; e++) {
            const int lin = tid + e * 256;          // 0..1023
            const int t = lin >> 3, s4 = (lin & 7) * 4;
            const size_t ei = (size_t)(t0 + t) * TT + s0 + s4;
            const uint2 u1 = *(const uint2*)&E1p[ei];
            const uint2 u2 = *(const uint2*)&E2p[ei];
            const uint2 u3 = *(const uint2*)&E3p[ei];
            const float2 e1a = __half22float2(*(const __half2*)&u1.x);
            const float2 e1b = __half22float2(*(const __half2*)&u1.y);
            const float2 e2a = __half22float2(*(const __half2*)&u2.x);
            const float2 e2b = __half22float2(*(const __half2*)&u2.y);
            const float2 e3a = __half22float2(*(const __half2*)&u3.x);
            const float2 e3b = __half22float2(*(const __half2*)&u3.y);
            const float4 a1v = make_float4(e1a.x * c1, e1a.y * c1, e1b.x * c1, e1b.y * c1);
            *(float4*)&a1p[ei] = a1v;               // scaled a1 -> d_out
            const float w0 = (a1v.x + e2a.x * c2 + e3a.x * c3) * third;
            const float w1 = (a1v.y + e2a.y * c2 + e3a.y * c3) * third;
            const float w2 = (a1v.z + e2b.x * c2 + e3b.x * c3) * third;
            const float w3 = (a1v.w + e2b.y * c2 + e3b.y * c3) * third;
            bf16 h0, l0, h1, l1, h2, l2, h3, l3;
            split1(w0, h0, l0); split1(w1, h1, l1);
            split1(w2, h2, l2); split1(w3, h3, l3);
            *(bf162*)&sW[0][t * 40 + s4]     = __halves2bfloat162(h0, h1);
            *(bf162*)&sW[0][t * 40 + s4 + 2] = __halves2bfloat162(h2, h3);
            *(bf162*)&sW[1][t * 40 + s4]     = __halves2bfloat162(l0, l1);
            *(bf162*)&sW[1][t * 40 + s4 + 2] = __halves2bfloat162(l2, l3);
        }
#pragma unroll
        for (int e = 0; e < 2; e++) {
            const int lin = tid + e * 256;          // 0..511
            const int s = lin >> 4, d4 = (lin & 15) * 4;
            float4 v = *(const float4*)&Vp[(size_t)(s0 + s) * EE + d4];
            bf16 h0, l0, h1, l1, h2, l2, h3, l3;
            split1(v.x, h0, l0); split1(v.y, h1, l1);
            split1(v.z, h2, l2); split1(v.w, h3, l3);
            *(bf162*)&sV[0][s * 72 + d4]     = __halves2bfloat162(h0, h1);
            *(bf162*)&sV[0][s * 72 + d4 + 2] = __halves2bfloat162(h2, h3);
            *(bf162*)&sV[1][s * 72 + d4]     = __halves2bfloat162(l0, l1);
            *(bf162*)&sV[1][s * 72 + d4 + 2] = __halves2bfloat162(l2, l3);
        }
        __syncthreads();
#pragma unroll
        for (int ks = 0; ks < 32; ks += 16) {
            uint32_t ah[4][4], al[4][4], bv[2][2][2];
            const int arow = wm * 64 + (lane & 15);
            const int ak = ks + (lane >> 4) * 8;
#pragma unroll
            for (int mt = 0; mt < 4; mt++) {
                ldsm4(s2u(&sW[0][(arow + mt * 16) * 40 + ak]), ah[mt][0], ah[mt][1], ah[mt][2], ah[mt][3]);
                ldsm4(s2u(&sW[1][(arow + mt * 16) * 40 + ak]), al[mt][0], al[mt][1], al[mt][2], al[mt][3]);
            }
            const int srow = ks + ((lane >> 3) & 1) * 8 + (lane & 7);
            const int dcol = wn * 16 + ((lane >> 4) & 1) * 8;
#pragma unroll
            for (int sg = 0; sg < 2; sg++) {
                uint32_t r0, r1, r2, r3;
                ldsm4t(s2u(&sV[sg][srow * 72 + dcol]), r0, r1, r2, r3);
                bv[sg][0][0] = r0; bv[sg][0][1] = r1;
                bv[sg][1][0] = r2; bv[sg][1][1] = r3;
            }
            // reordered passes: hi*hi, hi*lo, lo*hi (dep distance 8)
#pragma unroll
            for (int mt = 0; mt < 4; mt++)
#pragma unroll
                for (int nt = 0; nt < 2; nt++)
                    mma16816(acc[mt][nt], ah[mt], bv[0][nt]);
#pragma unroll
            for (int mt = 0; mt < 4; mt++)
#pragma unroll
                for (int nt = 0; nt < 2; nt++)
                    mma16816(acc[mt][nt], ah[mt], bv[1][nt]);
#pragma unroll
            for (int mt = 0; mt < 4; mt++)
#pragma unroll
                for (int nt = 0; nt < 2; nt++)
                    mma16816(acc[mt][nt], al[mt], bv[0][nt]);
        }
        __syncthreads();
    }

    const int r4 = lane >> 2, q2 = (lane & 3) * 2;
#pragma unroll
    for (int mt = 0; mt < 4; mt++) {
        const int trow = t0 + wm * 64 + mt * 16 + r4;
#pragma unroll
        for (int nt = 0; nt < 2; nt++) {
            const int col = h * HD + wn * 16 + nt * 8 + q2;
            bf16 h0, l0, h1, l1;
            const size_t base0 = (size_t)(b * TT + trow) * EE + col;
            split1(acc[mt][nt].x, h0, l0); split1(acc[mt][nt].y, h1, l1);
            *(bf162*)&g_AOhi[base0] = __halves2bfloat162(h0, h1);
            *(bf162*)&g_AOlo[base0] = __halves2bfloat162(l0, l1);
            const size_t base1 = (size_t)(b * TT + trow + 8) * EE + col;
            split1(acc[mt][nt].z, h0, l0); split1(acc[mt][nt].w, h1, l1);
            *(bf162*)&g_AOhi[base1] = __halves2bfloat162(h0, h1);
            *(bf162*)&g_AOlo[base1] = __halves2bfloat162(l0, l1);
        }
    }
}

// ---------------- launch ------------------------------------------------
extern "C" void kernel_launch(void* const* d_in, const int* in_sizes, int n_in,
                              void* d_out, int out_size)
{
    const float* q1  = (const float*)d_in[0];
    const float* q2  = (const float*)d_in[1];
    const float* key = (const float*)d_in[2];
    const float* val = (const float*)d_in[3];
    const float* Wq  = (const float*)d_in[4];
    const float* bq  = (const float*)d_in[5];
    const float* Wq2 = (const float*)d_in[6];
    const float* bq2 = (const float*)d_in[7];
    const float* Wq3 = (const float*)d_in[8];
    const float* bq3 = (const float*)d_in[9];
    const float* Wk  = (const float*)d_in[10];
    const float* bk  = (const float*)d_in[11];
    const float* Wv  = (const float*)d_in[12];
    const float* bv  = (const float*)d_in[13];
    const float* Wo  = (const float*)d_in[14];
    const float* bo  = (const float*)d_in[15];

    float* out = (float*)d_out;                      // [B,T,E]
    float* a1  = out + (size_t)BB * TT * EE;         // [B,H,T,T]

    bf16 *Xhi, *Xlo, *Whi, *Wlo, *Qhi, *Qlo, *AOhi, *AOlo;
    float* V;
    cudaGetSymbolAddress((void**)&Xhi, g_Xhi);
    cudaGetSymbolAddress((void**)&Xlo, g_Xlo);
    cudaGetSymbolAddress((void**)&Whi, g_Whi);
    cudaGetSymbolAddress((void**)&Wlo, g_Wlo);
    cudaGetSymbolAddress((void**)&Qhi, g_Qhi);
    cudaGetSymbolAddress((void**)&Qlo, g_Qlo);
    cudaGetSymbolAddress((void**)&AOhi, g_AOhi);
    cudaGetSymbolAddress((void**)&AOlo, g_AOlo);
    cudaGetSymbolAddress((void**)&V, g_V);

    cudaFuncSetAttribute(k_gemm_x3, cudaFuncAttributeMaxDynamicSharedMemorySize, GEMM_SMEM);
    cudaFuncSetAttribute(k_score,   cudaFuncAttributeMaxDynamicSharedMemorySize, SC_SMEM);

    k_zero_sums<<<1, 128>>>();

    // splits
    SplitArgs si = {};
    const float* xs[4] = { q1, q2, key, val };
    for (int i = 0; i < 4; i++) {
        si.src[i] = xs[i];
        si.hi[i] = Xhi + (size_t)i * NTOK * EE;
        si.lo[i] = Xlo + (size_t)i * NTOK * EE;
    }
    k_split<<<dim3((NTOK * EE / 4) / 256, 4), 256>>>(si, NTOK * EE / 4);

    SplitArgs sw = {};
    const float* ws[6] = { Wq, Wq2, Wq3, Wk, Wv, Wo };
    for (int i = 0; i < 6; i++) {
        sw.src[i] = ws[i];
        sw.hi[i] = Whi + (size_t)i * EE * EE;
        sw.lo[i] = Wlo + (size_t)i * EE * EE;
    }
    k_split<<<dim3((EE * EE / 4) / 256, 6), 256>>>(sw, EE * EE / 4);

    // projections: Q1,Q2,Q3,K (split out) + V (fp32 out) in one launch
    GArgs pa = {};
    const int aidx[5] = { 0, 1, 2, 2, 3 };           // q1, q2, key, key, value
    const float* bs[5] = { bq, bq2, bq3, bk, bv };
    for (int p = 0; p < 5; p++) {
        pa.g[p].Ahi = Xhi + (size_t)aidx[p] * NTOK * EE;
        pa.g[p].Alo = Xlo + (size_t)aidx[p] * NTOK * EE;
        pa.g[p].Whi = Whi + (size_t)p * EE * EE;
        pa.g[p].Wlo = Wlo + (size_t)p * EE * EE;
        pa.g[p].bias = bs[p];
        if (p < 4) {
            pa.g[p].Chi = Qhi + (size_t)p * NTOK * EE;
            pa.g[p].Clo = Qlo + (size_t)p * NTOK * EE;
            pa.g[p].Cf = nullptr;
        } else {
            pa.g[p].Chi = nullptr; pa.g[p].Clo = nullptr;
            pa.g[p].Cf = V;
        }
    }
    k_gemm_x3<<<dim3(EE / 128, NTOK / 128, 5), 256, GEMM_SMEM>>>(pa);

    k_score<<<dim3(TT / 128, TT / 128, 3 * NBH), 256, SC_SMEM>>>();

    k_av<<<dim3(TT / 128, NBH), 256>>>(a1);

    GArgs fo = {};
    fo.g[0].Ahi = AOhi; fo.g[0].Alo = AOlo;
    fo.g[0].Whi = Whi + (size_t)5 * EE * EE;
    fo.g[0].Wlo = Wlo + (size_t)5 * EE * EE;
    fo.g[0].bias = bo;
    fo.g[0].Chi = nullptr; fo.g[0].Clo = nullptr;
    fo.g[0].Cf = out;
    k_gemm_x3<<<dim3(EE / 128, NTOK / 128, 1), 256, GEMM_SMEM>>>(fo);
}